// round 3
// baseline (speedup 1.0000x reference)
#include <cuda_runtime.h>

#define NN 100000
#define EE 3200000
#define HH 64
#define NBSCAN 98

// ---------------- scratch (static device globals; no allocation) ----------------
__device__ int   g_deg[NN];
__device__ int   g_rowptr[NN + 1];
__device__ int   g_cursor[NN];
__device__ int   g_col[EE];
__device__ float g_dinv[NN];
__device__ __align__(16) float g_bufA[NN * HH];
__device__ __align__(16) float g_bufB[NN * HH];
__device__ int   g_part[128];
__device__ int   g_is64;

// ---------------- prep: edge dtype detect + zero degrees ----------------
// int64 edges (values < 2^31, LE): odd int32 words are all zero.
__global__ void k_prep(const int* __restrict__ ei32) {
    int i = blockIdx.x * blockDim.x + threadIdx.x;
    if (i < NN) g_deg[i] = 0;
    if (blockIdx.x == 0 && threadIdx.x == 0) {
        int z = 0;
        for (int k = 1; k < 4096; k += 2) z += (ei32[k] == 0);
        g_is64 = (z >= 1536) ? 1 : 0;
    }
}

// load two consecutive edge ids (base element index must be even)
__device__ __forceinline__ int2 edge_pair(const void* ei, size_t idx2) {
    if (g_is64) {
        longlong2 v = ((const longlong2*)ei)[idx2];
        return make_int2((int)v.x, (int)v.y);
    }
    return ((const int2*)ei)[idx2];
}

// ---------------- CSR build ----------------
__global__ void k_deg(const void* __restrict__ ei) {
    int e2 = blockIdx.x * blockDim.x + threadIdx.x;   // pair index
    if (e2 < EE / 2) {
        int2 d = edge_pair(ei, (size_t)(EE / 2) + e2);  // dst pairs
        atomicAdd(&g_deg[d.x], 1);
        atomicAdd(&g_deg[d.y], 1);
    }
}

// exclusive scan of g_deg -> g_rowptr, 1024 elems/block (256 thr x 4)
__global__ void k_scan1() {
    __shared__ int s[256];
    int t = threadIdx.x;
    int base = blockIdx.x * 1024 + t * 4;
    int v[4]; int sum = 0;
#pragma unroll
    for (int r = 0; r < 4; r++) { int i = base + r; v[r] = (i < NN) ? g_deg[i] : 0; sum += v[r]; }
    s[t] = sum;
    __syncthreads();
    for (int off = 1; off < 256; off <<= 1) {
        int x = (t >= off) ? s[t - off] : 0;
        __syncthreads();
        s[t] += x;
        __syncthreads();
    }
    int run = s[t] - sum;  // exclusive prefix within block
#pragma unroll
    for (int r = 0; r < 4; r++) { int i = base + r; if (i < NN) g_rowptr[i] = run; run += v[r]; }
    if (t == 255) g_part[blockIdx.x] = s[255];
}

// merged scan2+scan3: each block re-scans the 98 partials locally, then applies offset
__global__ void k_scan23() {
    __shared__ int s[NBSCAN];
    int t = threadIdx.x;
    if (t < NBSCAN) s[t] = g_part[t];
    __syncthreads();
    if (t == 0) {
        int run = 0;
        for (int i = 0; i < NBSCAN; i++) { int tmp = s[i]; s[i] = run; run += tmp; }
    }
    __syncthreads();
    int off = s[blockIdx.x];
    int base = blockIdx.x * 1024 + t * 4;
#pragma unroll
    for (int r = 0; r < 4; r++) {
        int i = base + r;
        if (i < NN) {
            int rp = g_rowptr[i] + off;
            g_rowptr[i] = rp;
            g_cursor[i] = rp;
            g_dinv[i] = rsqrtf((float)g_deg[i] + 1.0f);
        }
    }
    if (blockIdx.x == 0 && t == 0) g_rowptr[NN] = EE;
}

__global__ void k_fill(const void* __restrict__ ei) {
    int e2 = blockIdx.x * blockDim.x + threadIdx.x;
    if (e2 < EE / 2) {
        int2 s = edge_pair(ei, (size_t)e2);
        int2 d = edge_pair(ei, (size_t)(EE / 2) + e2);
        int p0 = atomicAdd(&g_cursor[d.x], 1);
        g_col[p0] = s.x;
        int p1 = atomicAdd(&g_cursor[d.y], 1);
        g_col[p1] = s.y;
    }
}

// ---------------- fused encoders + GCN0 linear : hs0 = dinv .* (relu-concat @ W0) ----------------
__global__ void __launch_bounds__(256) k_enc0(
    const float* __restrict__ xf, const float* __restrict__ xw, const float* __restrict__ xt,
    const float* __restrict__ wf, const float* __restrict__ bfir,
    const float* __restrict__ ww, const float* __restrict__ bwea,
    const float* __restrict__ wt, const float* __restrict__ bter,
    const float* __restrict__ W0)
{
    extern __shared__ __align__(16) float sm[];
    float* Ws   = sm;            // 192*64 = 12288
    float* Wenc = Ws + 12288;    // 30*64  = 1920
    float* Benc = Wenc + 1920;   // 192
    float* xs   = Benc + 192;    // 64*196 = 12544
    float* raw  = xs + 12544;    // 64*32  = 2048
    const int t = threadIdx.x;

    for (int i = t; i < 12288; i += 256) Ws[i] = W0[i];
    for (int i = t; i < 512;  i += 256) Wenc[i] = wf[i];
    for (int i = t; i < 768;  i += 256) Wenc[512 + i] = ww[i];
    for (int i = t; i < 640;  i += 256) Wenc[1280 + i] = wt[i];
    if (t < 64) { Benc[t] = bfir[t]; Benc[64 + t] = bwea[t]; Benc[128 + t] = bter[t]; }

    const int n0g = blockIdx.x * 64;
    for (int i = t; i < 512; i += 256) { int n = i >> 3, k = i & 7;  int gn = n0g + n; raw[n * 32 + k]      = (gn < NN) ? xf[gn * 8 + k]  : 0.f; }
    for (int i = t; i < 768; i += 256) { int n = i / 12, k = i % 12; int gn = n0g + n; raw[n * 32 + 8 + k]  = (gn < NN) ? xw[gn * 12 + k] : 0.f; }
    for (int i = t; i < 640; i += 256) { int n = i / 10, k = i % 10; int gn = n0g + n; raw[n * 32 + 20 + k] = (gn < NN) ? xt[gn * 10 + k] : 0.f; }
    __syncthreads();

    // stage A: per-node 192-dim encoded features (relu of 3 small matmuls)
    for (int i = t; i < 12288; i += 256) {
        int n = i / 192, c = i % 192;
        int mod = c >> 6, cc = c & 63;
        int koff = (mod == 0) ? 0 : ((mod == 1) ? 8 : 20);
        int kn   = (mod == 0) ? 8 : ((mod == 1) ? 12 : 10);
        const float* wr = Wenc + ((mod == 0) ? 0 : ((mod == 1) ? 512 : 1280));
        float v = Benc[c];
        for (int k = 0; k < kn; k++) v = fmaf(raw[n * 32 + koff + k], wr[k * 64 + cc], v);
        xs[n * 196 + c] = fmaxf(v, 0.f);
    }
    __syncthreads();

    // stage B: 64x64 output tile, 4x4 register micro-tile per thread
    const int cg = t & 15, ng = t >> 4;
    const int n0 = ng * 4, c0 = cg * 4;
    float acc[4][4];
#pragma unroll
    for (int i = 0; i < 4; i++)
#pragma unroll
        for (int j = 0; j < 4; j++) acc[i][j] = 0.f;

#pragma unroll 4
    for (int k = 0; k < 192; k++) {
        float4 b = *(const float4*)&Ws[k * 64 + c0];
#pragma unroll
        for (int i = 0; i < 4; i++) {
            float a = xs[(n0 + i) * 196 + k];
            acc[i][0] = fmaf(a, b.x, acc[i][0]);
            acc[i][1] = fmaf(a, b.y, acc[i][1]);
            acc[i][2] = fmaf(a, b.z, acc[i][2]);
            acc[i][3] = fmaf(a, b.w, acc[i][3]);
        }
    }
#pragma unroll
    for (int i = 0; i < 4; i++) {
        int gn = n0g + n0 + i;
        if (gn < NN) {
            float di = g_dinv[gn];
            float4 o = make_float4(di * acc[i][0], di * acc[i][1], di * acc[i][2], di * acc[i][3]);
            *(float4*)&g_bufA[(size_t)gn * 64 + c0] = o;
        }
    }
}

// ---------------- GCN linear : hs = dinv .* (x @ W) , 128-node tile, 8x4 micro-tile ----------------
__global__ void __launch_bounds__(256) k_lin(const float* __restrict__ W, int src_is_A)
{
    __shared__ __align__(16) float Ws[4096];
    __shared__ __align__(16) float xs[128 * 68];
    const float* x = src_is_A ? g_bufA : g_bufB;
    float* out     = src_is_A ? g_bufB : g_bufA;
    const int t = threadIdx.x;
    for (int i = t; i < 4096; i += 256) Ws[i] = W[i];

    const int n0g = blockIdx.x * 128;
    for (int i = t; i < 2048; i += 256) {
        int n = i >> 4, k4 = i & 15;
        int gn = n0g + n;
        float4 v = (gn < NN) ? *(const float4*)&x[(size_t)gn * 64 + k4 * 4] : make_float4(0, 0, 0, 0);
        *(float4*)&xs[n * 68 + k4 * 4] = v;
    }
    __syncthreads();

    const int cg = t & 15, rg = t >> 4;
    const int n0 = rg * 8, c0 = cg * 4;
    float acc[8][4];
#pragma unroll
    for (int i = 0; i < 8; i++)
#pragma unroll
        for (int j = 0; j < 4; j++) acc[i][j] = 0.f;

#pragma unroll 4
    for (int k = 0; k < 64; k++) {
        float4 b = *(const float4*)&Ws[k * 64 + c0];
#pragma unroll
        for (int i = 0; i < 8; i++) {
            float a = xs[(n0 + i) * 68 + k];
            acc[i][0] = fmaf(a, b.x, acc[i][0]);
            acc[i][1] = fmaf(a, b.y, acc[i][1]);
            acc[i][2] = fmaf(a, b.z, acc[i][2]);
            acc[i][3] = fmaf(a, b.w, acc[i][3]);
        }
    }
#pragma unroll
    for (int i = 0; i < 8; i++) {
        int gn = n0g + n0 + i;
        if (gn < NN) {
            float di = g_dinv[gn];
            float4 o = make_float4(di * acc[i][0], di * acc[i][1], di * acc[i][2], di * acc[i][3]);
            *(float4*)&out[(size_t)gn * 64 + c0] = o;
        }
    }
}

// ---------------- gather aggregation : x_out = relu(dinv_i * (sum_j hs_j + hs_i) + b) ----------------
// 2 nodes per warp (16 lanes each), float4 per lane, packed f32x2 accumulation.
__global__ void __launch_bounds__(256) k_gather(int src_is_A, const float* __restrict__ bias)
{
    const float* hs = src_is_A ? g_bufA : g_bufB;
    float* out      = src_is_A ? g_bufB : g_bufA;
    const int lane = threadIdx.x & 31;
    const int warp = threadIdx.x >> 5;
    const int half = lane >> 4;        // 0 or 1
    const int hl   = lane & 15;        // lane within half
    const int node = blockIdx.x * 16 + warp * 2 + half;   // NN divisible by 16

    const int beg = g_rowptr[node], end = g_rowptr[node + 1];

    // accumulate as packed f32x2 pairs
    ulonglong2 accp = *(const ulonglong2*)&hs[(size_t)node * 64 + hl * 4];  // self-loop term

    int p = beg;
    while (p < end) {
        int cnt = min(16, end - p);
        int idx = (hl < cnt) ? g_col[p + hl] : 0;
        int other = __shfl_xor_sync(0xffffffffu, cnt, 16);
        int m = cnt > other ? cnt : other;
        for (int tt = 0; tt < m; tt++) {
            int j = __shfl_sync(0xffffffffu, idx, (half << 4) + tt);
            if (tt < cnt) {
                ulonglong2 v = *(const ulonglong2*)&hs[(size_t)j * 64 + hl * 4];
                asm("add.rn.f32x2 %0, %0, %1;" : "+l"(accp.x) : "l"(v.x));
                asm("add.rn.f32x2 %0, %0, %1;" : "+l"(accp.y) : "l"(v.y));
            }
        }
        p += cnt;
    }

    float di = g_dinv[node];
    float4 b4 = *(const float4*)&bias[hl * 4];
    float2 lo = *(float2*)&accp.x;
    float2 hi = *(float2*)&accp.y;
    float4 o;
    o.x = fmaxf(fmaf(di, lo.x, b4.x), 0.f);
    o.y = fmaxf(fmaf(di, lo.y, b4.y), 0.f);
    o.z = fmaxf(fmaf(di, hi.x, b4.z), 0.f);
    o.w = fmaxf(fmaf(di, hi.y, b4.w), 0.f);
    *(float4*)&out[(size_t)node * 64 + hl * 4] = o;
}

// ---------------- output MLP : out = relu(x @ W1 + b1) @ W2 + b2 ----------------
__global__ void __launch_bounds__(256) k_out(int src_is_A,
    const float* __restrict__ W1, const float* __restrict__ B1,
    const float* __restrict__ W2, const float* __restrict__ B2,
    float* __restrict__ out)
{
    const float* x = src_is_A ? g_bufA : g_bufB;
    __shared__ float W1s[2048];
    __shared__ float W2s[32];
    __shared__ float B1s[32];
    __shared__ float xsh[8][64];
    const int t = threadIdx.x;
    for (int i = t; i < 2048; i += 256) W1s[i] = W1[i];
    if (t < 32) { W2s[t] = W2[t]; B1s[t] = B1[t]; }
    __syncthreads();

    const int lane = t & 31, w = t >> 5;
    const int node = blockIdx.x * 8 + w;
    if (node < NN) {
        xsh[w][lane]      = x[(size_t)node * 64 + lane];
        xsh[w][32 + lane] = x[(size_t)node * 64 + 32 + lane];
        __syncwarp();
        float m = B1s[lane];
#pragma unroll
        for (int k = 0; k < 64; k++) m = fmaf(xsh[w][k], W1s[k * 32 + lane], m);
        m = fmaxf(m, 0.f) * W2s[lane];
#pragma unroll
        for (int off = 16; off; off >>= 1) m += __shfl_xor_sync(0xffffffffu, m, off);
        if (lane == 0) out[node] = m + B2[0];
    }
}

// ---------------- launch ----------------
extern "C" void kernel_launch(void* const* d_in, const int* in_sizes, int n_in,
                              void* d_out, int out_size)
{
    const float* xf  = (const float*)d_in[0];
    const float* xw  = (const float*)d_in[1];
    const float* xt  = (const float*)d_in[2];
    const void*  ei  = d_in[3];
    const float* wf  = (const float*)d_in[4];
    const float* bf  = (const float*)d_in[5];
    const float* ww  = (const float*)d_in[6];
    const float* bw  = (const float*)d_in[7];
    const float* wt  = (const float*)d_in[8];
    const float* bt  = (const float*)d_in[9];
    const float* w0  = (const float*)d_in[10];
    const float* b0  = (const float*)d_in[11];
    const float* w1  = (const float*)d_in[12];
    const float* b1  = (const float*)d_in[13];
    const float* w2  = (const float*)d_in[14];
    const float* b2  = (const float*)d_in[15];
    const float* ow1 = (const float*)d_in[16];
    const float* ob1 = (const float*)d_in[17];
    const float* ow2 = (const float*)d_in[18];
    const float* ob2 = (const float*)d_in[19];
    float* out = (float*)d_out;

    const int ENC_SMEM = (12288 + 1920 + 192 + 12544 + 2048) * 4;  // 115968 B
    cudaFuncSetAttribute(k_enc0, cudaFuncAttributeMaxDynamicSharedMemorySize, ENC_SMEM);

    const int encTiles = (NN + 63) / 64;    // 1563
    const int linTiles = (NN + 127) / 128;  // 782
    const int gBlocks  = NN / 16;           // 6250
    const int oBlocks  = (NN + 7) / 8;      // 12500
    const int ePairs   = EE / 2;

    // CSR build (by destination) + dinv
    k_prep<<<(NN + 255) / 256, 256>>>((const int*)ei);
    k_deg<<<(ePairs + 255) / 256, 256>>>(ei);
    k_scan1<<<NBSCAN, 256>>>();
    k_scan23<<<NBSCAN, 256>>>();
    k_fill<<<(ePairs + 255) / 256, 256>>>(ei);

    // layer 0: fused encoders + linear -> hs0 (A), gather -> x1 (B)
    k_enc0<<<encTiles, 256, ENC_SMEM>>>(xf, xw, xt, wf, bf, ww, bw, wt, bt, w0);
    k_gather<<<gBlocks, 256>>>(1, b0);
    // layer 1
    k_lin<<<linTiles, 256>>>(w1, 0);        // B -> A
    k_gather<<<gBlocks, 256>>>(1, b1);      // A -> B
    // layer 2
    k_lin<<<linTiles, 256>>>(w2, 0);        // B -> A
    k_gather<<<gBlocks, 256>>>(1, b2);      // A -> B
    // output MLP
    k_out<<<oBlocks, 256>>>(0, ow1, ob1, ow2, ob2, out);
}

// round 4
// speedup vs baseline: 1.1185x; 1.1185x over previous
#include <cuda_runtime.h>
#include <cuda_fp16.h>

#define NN 100000
#define EE 3200000
#define HH 64
#define NBSCAN 98

// ---------------- scratch (static device globals; no allocation) ----------------
__device__ int   g_deg[NN];
__device__ int   g_rowptr[NN + 1];
__device__ int   g_cursor[NN];
__device__ int   g_col[EE];
__device__ float g_dinv[NN];
__device__ __align__(16) __half g_hs[NN * HH];   // scaled features for gather (fp16)
__device__ __align__(16) float  g_x[NN * HH];    // layer activations (fp32)
__device__ int   g_part[128];
__device__ int   g_is64;

// ---------------- prep: zero degrees + parallel edge-dtype detect ----------------
// int64 edges (values < 2^31, LE): odd int32 words are all zero.
__global__ void k_prep(const int* __restrict__ ei32) {
    int i = blockIdx.x * blockDim.x + threadIdx.x;
    if (i < NN) g_deg[i] = 0;
    if (blockIdx.x == 0) {
        __shared__ int cnt;
        if (threadIdx.x == 0) cnt = 0;
        __syncthreads();
        int z = 0;
#pragma unroll
        for (int r = 0; r < 8; r++) {
            int k = 1 + 2 * (threadIdx.x * 8 + r);   // odd words 1..4095
            z += (ei32[k] == 0);
        }
#pragma unroll
        for (int o = 16; o; o >>= 1) z += __shfl_xor_sync(0xffffffffu, z, o);
        if ((threadIdx.x & 31) == 0) atomicAdd(&cnt, z);
        __syncthreads();
        if (threadIdx.x == 0) g_is64 = (cnt >= 1536) ? 1 : 0;
    }
}

// load two consecutive edge ids (base element index must be even)
__device__ __forceinline__ int2 edge_pair(const void* ei, size_t idx2) {
    if (g_is64) {
        longlong2 v = ((const longlong2*)ei)[idx2];
        return make_int2((int)v.x, (int)v.y);
    }
    return ((const int2*)ei)[idx2];
}

// ---------------- CSR build ----------------
__global__ void k_deg(const void* __restrict__ ei) {
    int e2 = blockIdx.x * blockDim.x + threadIdx.x;   // pair index
    if (e2 < EE / 2) {
        int2 d = edge_pair(ei, (size_t)(EE / 2) + e2);  // dst pairs
        atomicAdd(&g_deg[d.x], 1);
        atomicAdd(&g_deg[d.y], 1);
    }
}

__global__ void k_scan1() {
    __shared__ int s[256];
    int t = threadIdx.x;
    int base = blockIdx.x * 1024 + t * 4;
    int v[4]; int sum = 0;
#pragma unroll
    for (int r = 0; r < 4; r++) { int i = base + r; v[r] = (i < NN) ? g_deg[i] : 0; sum += v[r]; }
    s[t] = sum;
    __syncthreads();
    for (int off = 1; off < 256; off <<= 1) {
        int x = (t >= off) ? s[t - off] : 0;
        __syncthreads();
        s[t] += x;
        __syncthreads();
    }
    int run = s[t] - sum;
#pragma unroll
    for (int r = 0; r < 4; r++) { int i = base + r; if (i < NN) g_rowptr[i] = run; run += v[r]; }
    if (t == 255) g_part[blockIdx.x] = s[255];
}

__global__ void k_scan23() {
    __shared__ int s[NBSCAN];
    int t = threadIdx.x;
    if (t < NBSCAN) s[t] = g_part[t];
    __syncthreads();
    if (t == 0) {
        int run = 0;
        for (int i = 0; i < NBSCAN; i++) { int tmp = s[i]; s[i] = run; run += tmp; }
    }
    __syncthreads();
    int off = s[blockIdx.x];
    int base = blockIdx.x * 1024 + t * 4;
#pragma unroll
    for (int r = 0; r < 4; r++) {
        int i = base + r;
        if (i < NN) {
            int rp = g_rowptr[i] + off;
            g_rowptr[i] = rp;
            g_cursor[i] = rp;
            g_dinv[i] = rsqrtf((float)g_deg[i] + 1.0f);
        }
    }
    if (blockIdx.x == 0 && t == 0) g_rowptr[NN] = EE;
}

__global__ void k_fill(const void* __restrict__ ei) {
    int e2 = blockIdx.x * blockDim.x + threadIdx.x;
    if (e2 < EE / 2) {
        int2 s = edge_pair(ei, (size_t)e2);
        int2 d = edge_pair(ei, (size_t)(EE / 2) + e2);
        int p0 = atomicAdd(&g_cursor[d.x], 1);
        g_col[p0] = s.x;
        int p1 = atomicAdd(&g_cursor[d.y], 1);
        g_col[p1] = s.y;
    }
}

// pack float4 -> 4 halves (uint2)
__device__ __forceinline__ uint2 pack_h4(float a, float b, float c, float d) {
    __half2 lo = __floats2half2_rn(a, b);
    __half2 hi = __floats2half2_rn(c, d);
    uint2 r;
    r.x = *(unsigned*)&lo;
    r.y = *(unsigned*)&hi;
    return r;
}

// ---------------- fused encoders + GCN0 linear : hs0 = fp16(dinv .* (relu-concat @ W0)) ----------------
__global__ void __launch_bounds__(256) k_enc0(
    const float* __restrict__ xf, const float* __restrict__ xw, const float* __restrict__ xt,
    const float* __restrict__ wf, const float* __restrict__ bfir,
    const float* __restrict__ ww, const float* __restrict__ bwea,
    const float* __restrict__ wt, const float* __restrict__ bter,
    const float* __restrict__ W0)
{
    extern __shared__ __align__(16) float sm[];
    float* Ws   = sm;            // 192*64 = 12288
    float* Wenc = Ws + 12288;    // 30*64  = 1920
    float* Benc = Wenc + 1920;   // 192
    float* xs   = Benc + 192;    // 64*196 = 12544
    float* raw  = xs + 12544;    // 64*32  = 2048
    const int t = threadIdx.x;

    for (int i = t; i < 12288; i += 256) Ws[i] = W0[i];
    for (int i = t; i < 512;  i += 256) Wenc[i] = wf[i];
    for (int i = t; i < 768;  i += 256) Wenc[512 + i] = ww[i];
    for (int i = t; i < 640;  i += 256) Wenc[1280 + i] = wt[i];
    if (t < 64) { Benc[t] = bfir[t]; Benc[64 + t] = bwea[t]; Benc[128 + t] = bter[t]; }

    const int n0g = blockIdx.x * 64;
    for (int i = t; i < 512; i += 256) { int n = i >> 3, k = i & 7;  int gn = n0g + n; raw[n * 32 + k]      = (gn < NN) ? xf[gn * 8 + k]  : 0.f; }
    for (int i = t; i < 768; i += 256) { int n = i / 12, k = i % 12; int gn = n0g + n; raw[n * 32 + 8 + k]  = (gn < NN) ? xw[gn * 12 + k] : 0.f; }
    for (int i = t; i < 640; i += 256) { int n = i / 10, k = i % 10; int gn = n0g + n; raw[n * 32 + 20 + k] = (gn < NN) ? xt[gn * 10 + k] : 0.f; }
    __syncthreads();

    for (int i = t; i < 12288; i += 256) {
        int n = i / 192, c = i % 192;
        int mod = c >> 6, cc = c & 63;
        int koff = (mod == 0) ? 0 : ((mod == 1) ? 8 : 20);
        int kn   = (mod == 0) ? 8 : ((mod == 1) ? 12 : 10);
        const float* wr = Wenc + ((mod == 0) ? 0 : ((mod == 1) ? 512 : 1280));
        float v = Benc[c];
        for (int k = 0; k < kn; k++) v = fmaf(raw[n * 32 + koff + k], wr[k * 64 + cc], v);
        xs[n * 196 + c] = fmaxf(v, 0.f);
    }
    __syncthreads();

    const int cg = t & 15, ng = t >> 4;
    const int n0 = ng * 4, c0 = cg * 4;
    float acc[4][4];
#pragma unroll
    for (int i = 0; i < 4; i++)
#pragma unroll
        for (int j = 0; j < 4; j++) acc[i][j] = 0.f;

#pragma unroll 4
    for (int k = 0; k < 192; k++) {
        float4 b = *(const float4*)&Ws[k * 64 + c0];
#pragma unroll
        for (int i = 0; i < 4; i++) {
            float a = xs[(n0 + i) * 196 + k];
            acc[i][0] = fmaf(a, b.x, acc[i][0]);
            acc[i][1] = fmaf(a, b.y, acc[i][1]);
            acc[i][2] = fmaf(a, b.z, acc[i][2]);
            acc[i][3] = fmaf(a, b.w, acc[i][3]);
        }
    }
#pragma unroll
    for (int i = 0; i < 4; i++) {
        int gn = n0g + n0 + i;
        if (gn < NN) {
            float di = g_dinv[gn];
            uint2 o = pack_h4(di * acc[i][0], di * acc[i][1], di * acc[i][2], di * acc[i][3]);
            *(uint2*)&g_hs[(size_t)gn * 64 + c0] = o;
        }
    }
}

// ---------------- GCN linear : hs = fp16(dinv .* (x @ W)) , 128-node tile, 8x4 micro-tile ----------------
__global__ void __launch_bounds__(256) k_lin(const float* __restrict__ W)
{
    __shared__ __align__(16) float Ws[4096];
    __shared__ __align__(16) float xs[128 * 68];
    const int t = threadIdx.x;
    for (int i = t; i < 4096; i += 256) Ws[i] = W[i];

    const int n0g = blockIdx.x * 128;
    for (int i = t; i < 2048; i += 256) {
        int n = i >> 4, k4 = i & 15;
        int gn = n0g + n;
        float4 v = (gn < NN) ? *(const float4*)&g_x[(size_t)gn * 64 + k4 * 4] : make_float4(0, 0, 0, 0);
        *(float4*)&xs[n * 68 + k4 * 4] = v;
    }
    __syncthreads();

    const int cg = t & 15, rg = t >> 4;
    const int n0 = rg * 8, c0 = cg * 4;
    float acc[8][4];
#pragma unroll
    for (int i = 0; i < 8; i++)
#pragma unroll
        for (int j = 0; j < 4; j++) acc[i][j] = 0.f;

#pragma unroll 4
    for (int k = 0; k < 64; k++) {
        float4 b = *(const float4*)&Ws[k * 64 + c0];
#pragma unroll
        for (int i = 0; i < 8; i++) {
            float a = xs[(n0 + i) * 68 + k];
            acc[i][0] = fmaf(a, b.x, acc[i][0]);
            acc[i][1] = fmaf(a, b.y, acc[i][1]);
            acc[i][2] = fmaf(a, b.z, acc[i][2]);
            acc[i][3] = fmaf(a, b.w, acc[i][3]);
        }
    }
#pragma unroll
    for (int i = 0; i < 8; i++) {
        int gn = n0g + n0 + i;
        if (gn < NN) {
            float di = g_dinv[gn];
            uint2 o = pack_h4(di * acc[i][0], di * acc[i][1], di * acc[i][2], di * acc[i][3]);
            *(uint2*)&g_hs[(size_t)gn * 64 + c0] = o;
        }
    }
}

// ---------------- gather aggregation : x = relu(dinv_i * (sum_j hs_j + hs_i) + b) ----------------
// 2 nodes per warp (16 lanes each); lane holds 4 features (fp16 in memory, fp32 accum).
__global__ void __launch_bounds__(256) k_gather(const float* __restrict__ bias)
{
    const int lane = threadIdx.x & 31;
    const int warp = threadIdx.x >> 5;
    const int half = lane >> 4;
    const int hl   = lane & 15;
    const int node = blockIdx.x * 16 + warp * 2 + half;   // NN divisible by 16

    const int beg = g_rowptr[node], end = g_rowptr[node + 1];

    uint2 self = *(const uint2*)&g_hs[(size_t)node * 64 + hl * 4];
    float2 acc0 = __half22float2(*(__half2*)&self.x);
    float2 acc1 = __half22float2(*(__half2*)&self.y);

    int p = beg;
    while (p < end) {
        int cnt = min(16, end - p);
        int idx = (hl < cnt) ? g_col[p + hl] : 0;
        int other = __shfl_xor_sync(0xffffffffu, cnt, 16);
        int m = cnt > other ? cnt : other;
        for (int tt = 0; tt < m; tt++) {
            int j = __shfl_sync(0xffffffffu, idx, (half << 4) + tt);
            if (tt < cnt) {
                uint2 v = *(const uint2*)&g_hs[(size_t)j * 64 + hl * 4];
                float2 v0 = __half22float2(*(__half2*)&v.x);
                float2 v1 = __half22float2(*(__half2*)&v.y);
                acc0.x += v0.x; acc0.y += v0.y;
                acc1.x += v1.x; acc1.y += v1.y;
            }
        }
        p += cnt;
    }

    float di = g_dinv[node];
    float4 b4 = *(const float4*)&bias[hl * 4];
    float4 o;
    o.x = fmaxf(fmaf(di, acc0.x, b4.x), 0.f);
    o.y = fmaxf(fmaf(di, acc0.y, b4.y), 0.f);
    o.z = fmaxf(fmaf(di, acc1.x, b4.z), 0.f);
    o.w = fmaxf(fmaf(di, acc1.y, b4.w), 0.f);
    *(float4*)&g_x[(size_t)node * 64 + hl * 4] = o;
}

// ---------------- output MLP : out = relu(x @ W1 + b1) @ W2 + b2 ----------------
__global__ void __launch_bounds__(256) k_out(
    const float* __restrict__ W1, const float* __restrict__ B1,
    const float* __restrict__ W2, const float* __restrict__ B2,
    float* __restrict__ out)
{
    __shared__ float W1s[2048];
    __shared__ float W2s[32];
    __shared__ float B1s[32];
    __shared__ float xsh[8][64];
    const int t = threadIdx.x;
    for (int i = t; i < 2048; i += 256) W1s[i] = W1[i];
    if (t < 32) { W2s[t] = W2[t]; B1s[t] = B1[t]; }
    __syncthreads();

    const int lane = t & 31, w = t >> 5;
    const int node = blockIdx.x * 8 + w;
    if (node < NN) {
        xsh[w][lane]      = g_x[(size_t)node * 64 + lane];
        xsh[w][32 + lane] = g_x[(size_t)node * 64 + 32 + lane];
        __syncwarp();
        float m = B1s[lane];
#pragma unroll
        for (int k = 0; k < 64; k++) m = fmaf(xsh[w][k], W1s[k * 32 + lane], m);
        m = fmaxf(m, 0.f) * W2s[lane];
#pragma unroll
        for (int off = 16; off; off >>= 1) m += __shfl_xor_sync(0xffffffffu, m, off);
        if (lane == 0) out[node] = m + B2[0];
    }
}

// ---------------- launch ----------------
extern "C" void kernel_launch(void* const* d_in, const int* in_sizes, int n_in,
                              void* d_out, int out_size)
{
    const float* xf  = (const float*)d_in[0];
    const float* xw  = (const float*)d_in[1];
    const float* xt  = (const float*)d_in[2];
    const void*  ei  = d_in[3];
    const float* wf  = (const float*)d_in[4];
    const float* bf  = (const float*)d_in[5];
    const float* ww  = (const float*)d_in[6];
    const float* bw  = (const float*)d_in[7];
    const float* wt  = (const float*)d_in[8];
    const float* bt  = (const float*)d_in[9];
    const float* w0  = (const float*)d_in[10];
    const float* b0  = (const float*)d_in[11];
    const float* w1  = (const float*)d_in[12];
    const float* b1  = (const float*)d_in[13];
    const float* w2  = (const float*)d_in[14];
    const float* b2  = (const float*)d_in[15];
    const float* ow1 = (const float*)d_in[16];
    const float* ob1 = (const float*)d_in[17];
    const float* ow2 = (const float*)d_in[18];
    const float* ob2 = (const float*)d_in[19];
    float* out = (float*)d_out;

    const int ENC_SMEM = (12288 + 1920 + 192 + 12544 + 2048) * 4;  // 115968 B
    cudaFuncSetAttribute(k_enc0, cudaFuncAttributeMaxDynamicSharedMemorySize, ENC_SMEM);

    const int encTiles = (NN + 63) / 64;    // 1563
    const int linTiles = (NN + 127) / 128;  // 782
    const int gBlocks  = NN / 16;           // 6250
    const int oBlocks  = (NN + 7) / 8;      // 12500
    const int ePairs   = EE / 2;

    // CSR build (by destination) + dinv
    k_prep<<<(NN + 255) / 256, 256>>>((const int*)ei);
    k_deg<<<(ePairs + 255) / 256, 256>>>(ei);
    k_scan1<<<NBSCAN, 256>>>();
    k_scan23<<<NBSCAN, 256>>>();
    k_fill<<<(ePairs + 255) / 256, 256>>>(ei);

    // layer 0
    k_enc0<<<encTiles, 256, ENC_SMEM>>>(xf, xw, xt, wf, bf, ww, bw, wt, bt, w0);
    k_gather<<<gBlocks, 256>>>(b0);
    // layer 1
    k_lin<<<linTiles, 256>>>(w1);
    k_gather<<<gBlocks, 256>>>(b1);
    // layer 2
    k_lin<<<linTiles, 256>>>(w2);
    k_gather<<<gBlocks, 256>>>(b2);
    // output MLP
    k_out<<<oBlocks, 256>>>(ow1, ob1, ow2, ob2, out);
}

// round 5
// speedup vs baseline: 1.1764x; 1.0518x over previous
#include <cuda_runtime.h>
#include <cuda_fp16.h>

#define NN 100000
#define EE 3200000
#define HH 64
#define NBSCAN 98

// ---------------- scratch (static device globals; no allocation) ----------------
__device__ int   g_deg[NN];
__device__ int   g_rowptr[NN + 1];
__device__ int   g_cursor[NN];
__device__ int   g_col[EE];
__device__ float g_dinv[NN];
__device__ __align__(16) __half g_hs[NN * HH];   // scaled features for gather (fp16)
__device__ __align__(16) float  g_x[NN * HH];    // layer activations (fp32)
__device__ int   g_is64;
// decoupled-lookback scan state
__device__ volatile int g_bsum[NBSCAN];
__device__ volatile int g_bpre[NBSCAN];
__device__ volatile int g_bflag[NBSCAN];   // 0=none, 1=aggregate, 2=prefix

// ---------------- prep: zero degrees + scan flags + parallel edge-dtype detect ----------------
__global__ void k_prep(const int* __restrict__ ei32) {
    int i = blockIdx.x * blockDim.x + threadIdx.x;
    if (i < NN) g_deg[i] = 0;
    if (i < NBSCAN) { g_bflag[i] = 0; g_bsum[i] = 0; g_bpre[i] = 0; }
    if (blockIdx.x == 0) {
        __shared__ int cnt;
        if (threadIdx.x == 0) cnt = 0;
        __syncthreads();
        int z = 0;
#pragma unroll
        for (int r = 0; r < 8; r++) {
            int k = 1 + 2 * (threadIdx.x * 8 + r);   // odd words 1..4095
            z += (ei32[k] == 0);
        }
#pragma unroll
        for (int o = 16; o; o >>= 1) z += __shfl_xor_sync(0xffffffffu, z, o);
        if ((threadIdx.x & 31) == 0) atomicAdd(&cnt, z);
        __syncthreads();
        if (threadIdx.x == 0) g_is64 = (cnt >= 1536) ? 1 : 0;
    }
}

__device__ __forceinline__ int2 edge_pair(const void* ei, size_t idx2) {
    if (g_is64) {
        longlong2 v = ((const longlong2*)ei)[idx2];
        return make_int2((int)v.x, (int)v.y);
    }
    return ((const int2*)ei)[idx2];
}

// ---------------- CSR build ----------------
__global__ void k_deg(const void* __restrict__ ei) {
    int e2 = blockIdx.x * blockDim.x + threadIdx.x;
    if (e2 < EE / 2) {
        int2 d = edge_pair(ei, (size_t)(EE / 2) + e2);
        atomicAdd(&g_deg[d.x], 1);
        atomicAdd(&g_deg[d.y], 1);
    }
}

// single-pass exclusive scan with decoupled lookback (98 blocks, all resident)
__global__ void __launch_bounds__(256) k_scan() {
    __shared__ int s[256];
    __shared__ int sh_total, sh_exc;
    const int t = threadIdx.x;
    const int bid = blockIdx.x;
    int base = bid * 1024 + t * 4;
    int v[4]; int sum = 0;
#pragma unroll
    for (int r = 0; r < 4; r++) { int i = base + r; v[r] = (i < NN) ? g_deg[i] : 0; sum += v[r]; }
    s[t] = sum;
    __syncthreads();
    for (int off = 1; off < 256; off <<= 1) {
        int x = (t >= off) ? s[t - off] : 0;
        __syncthreads();
        s[t] += x;
        __syncthreads();
    }
    int run = s[t] - sum;           // exclusive prefix within block
    if (t == 255) {
        sh_total = s[255];
        g_bsum[bid] = s[255];
        __threadfence();
        if (bid == 0) { g_bpre[0] = s[255]; g_bflag[0] = 2; }
        else          { g_bflag[bid] = 1; }
        if (bid == 0) sh_exc = 0;
    }
    __syncthreads();

    // warp 0 lookback for exclusive prefix
    if (bid > 0 && t < 32) {
        int lane = t;
        int excl = 0;
        int j = bid - 1;
        while (true) {
            int jj = j - lane;
            int f = 0, val = 0;
            if (jj >= 0) {
                while ((f = g_bflag[jj]) == 0) { }
                val = (f == 2) ? g_bpre[jj] : g_bsum[jj];
            }
            unsigned ball = __ballot_sync(0xffffffffu, (jj >= 0) && (f == 2));
            int contrib;
            if (ball) {
                int l = __ffs(ball) - 1;     // smallest lane = nearest prefix block
                contrib = (lane <= l) ? val : 0;
            } else {
                contrib = (jj >= 0) ? val : 0;
            }
#pragma unroll
            for (int o = 16; o; o >>= 1) contrib += __shfl_xor_sync(0xffffffffu, contrib, o);
            excl += contrib;
            if (ball) break;
            j -= 32;
        }
        if (lane == 0) {
            sh_exc = excl;
            g_bpre[bid] = excl + sh_total;
            __threadfence();
            g_bflag[bid] = 2;
        }
    }
    __syncthreads();

    int exc = sh_exc;
#pragma unroll
    for (int r = 0; r < 4; r++) {
        int i = base + r;
        if (i < NN) {
            int rp = run + exc;
            g_rowptr[i] = rp;
            g_cursor[i] = rp;
            g_dinv[i] = rsqrtf((float)g_deg[i] + 1.0f);
        }
        run += v[r];
    }
    if (bid == 0 && t == 0) g_rowptr[NN] = EE;
}

__global__ void k_fill(const void* __restrict__ ei) {
    int e2 = blockIdx.x * blockDim.x + threadIdx.x;
    if (e2 < EE / 2) {
        int2 s = edge_pair(ei, (size_t)e2);
        int2 d = edge_pair(ei, (size_t)(EE / 2) + e2);
        int p0 = atomicAdd(&g_cursor[d.x], 1);
        g_col[p0] = s.x;
        int p1 = atomicAdd(&g_cursor[d.y], 1);
        g_col[p1] = s.y;
    }
}

// pack float4 -> 4 halves (uint2)
__device__ __forceinline__ uint2 pack_h4(float a, float b, float c, float d) {
    __half2 lo = __floats2half2_rn(a, b);
    __half2 hi = __floats2half2_rn(c, d);
    uint2 r;
    r.x = *(unsigned*)&lo;
    r.y = *(unsigned*)&hi;
    return r;
}

// ---------------- fused encoders + GCN0 linear : hs0 = fp16(dinv .* (relu-concat @ W0)) ----------------
__global__ void __launch_bounds__(256) k_enc0(
    const float* __restrict__ xf, const float* __restrict__ xw, const float* __restrict__ xt,
    const float* __restrict__ wf, const float* __restrict__ bfir,
    const float* __restrict__ ww, const float* __restrict__ bwea,
    const float* __restrict__ wt, const float* __restrict__ bter,
    const float* __restrict__ W0)
{
    extern __shared__ __align__(16) float sm[];
    float* Ws   = sm;            // 192*64 = 12288
    float* Wenc = Ws + 12288;    // 30*64  = 1920
    float* Benc = Wenc + 1920;   // 192
    float* xs   = Benc + 192;    // 64*196 = 12544
    float* raw  = xs + 12544;    // 64*32  = 2048
    const int t = threadIdx.x;

    for (int i = t; i < 12288; i += 256) Ws[i] = W0[i];
    for (int i = t; i < 512;  i += 256) Wenc[i] = wf[i];
    for (int i = t; i < 768;  i += 256) Wenc[512 + i] = ww[i];
    for (int i = t; i < 640;  i += 256) Wenc[1280 + i] = wt[i];
    if (t < 64) { Benc[t] = bfir[t]; Benc[64 + t] = bwea[t]; Benc[128 + t] = bter[t]; }

    const int n0g = blockIdx.x * 64;
    for (int i = t; i < 512; i += 256) { int n = i >> 3, k = i & 7;  int gn = n0g + n; raw[n * 32 + k]      = (gn < NN) ? xf[gn * 8 + k]  : 0.f; }
    for (int i = t; i < 768; i += 256) { int n = i / 12, k = i % 12; int gn = n0g + n; raw[n * 32 + 8 + k]  = (gn < NN) ? xw[gn * 12 + k] : 0.f; }
    for (int i = t; i < 640; i += 256) { int n = i / 10, k = i % 10; int gn = n0g + n; raw[n * 32 + 20 + k] = (gn < NN) ? xt[gn * 10 + k] : 0.f; }
    __syncthreads();

    for (int i = t; i < 12288; i += 256) {
        int n = i / 192, c = i % 192;
        int mod = c >> 6, cc = c & 63;
        int koff = (mod == 0) ? 0 : ((mod == 1) ? 8 : 20);
        int kn   = (mod == 0) ? 8 : ((mod == 1) ? 12 : 10);
        const float* wr = Wenc + ((mod == 0) ? 0 : ((mod == 1) ? 512 : 1280));
        float v = Benc[c];
        for (int k = 0; k < kn; k++) v = fmaf(raw[n * 32 + koff + k], wr[k * 64 + cc], v);
        xs[n * 196 + c] = fmaxf(v, 0.f);
    }
    __syncthreads();

    const int cg = t & 15, ng = t >> 4;
    const int n0 = ng * 4, c0 = cg * 4;
    float acc[4][4];
#pragma unroll
    for (int i = 0; i < 4; i++)
#pragma unroll
        for (int j = 0; j < 4; j++) acc[i][j] = 0.f;

#pragma unroll 4
    for (int k = 0; k < 192; k++) {
        float4 b = *(const float4*)&Ws[k * 64 + c0];
#pragma unroll
        for (int i = 0; i < 4; i++) {
            float a = xs[(n0 + i) * 196 + k];
            acc[i][0] = fmaf(a, b.x, acc[i][0]);
            acc[i][1] = fmaf(a, b.y, acc[i][1]);
            acc[i][2] = fmaf(a, b.z, acc[i][2]);
            acc[i][3] = fmaf(a, b.w, acc[i][3]);
        }
    }
#pragma unroll
    for (int i = 0; i < 4; i++) {
        int gn = n0g + n0 + i;
        if (gn < NN) {
            float di = g_dinv[gn];
            uint2 o = pack_h4(di * acc[i][0], di * acc[i][1], di * acc[i][2], di * acc[i][3]);
            *(uint2*)&g_hs[(size_t)gn * 64 + c0] = o;
        }
    }
}

// ---------------- GCN linear : hs = fp16(dinv .* (x @ W)) ----------------
__global__ void __launch_bounds__(256) k_lin(const float* __restrict__ W)
{
    __shared__ __align__(16) float Ws[4096];
    __shared__ __align__(16) float xs[128 * 68];
    const int t = threadIdx.x;
    for (int i = t; i < 4096; i += 256) Ws[i] = W[i];

    const int n0g = blockIdx.x * 128;
    for (int i = t; i < 2048; i += 256) {
        int n = i >> 4, k4 = i & 15;
        int gn = n0g + n;
        float4 v = (gn < NN) ? *(const float4*)&g_x[(size_t)gn * 64 + k4 * 4] : make_float4(0, 0, 0, 0);
        *(float4*)&xs[n * 68 + k4 * 4] = v;
    }
    __syncthreads();

    const int cg = t & 15, rg = t >> 4;
    const int n0 = rg * 8, c0 = cg * 4;
    float acc[8][4];
#pragma unroll
    for (int i = 0; i < 8; i++)
#pragma unroll
        for (int j = 0; j < 4; j++) acc[i][j] = 0.f;

#pragma unroll 4
    for (int k = 0; k < 64; k++) {
        float4 b = *(const float4*)&Ws[k * 64 + c0];
#pragma unroll
        for (int i = 0; i < 8; i++) {
            float a = xs[(n0 + i) * 68 + k];
            acc[i][0] = fmaf(a, b.x, acc[i][0]);
            acc[i][1] = fmaf(a, b.y, acc[i][1]);
            acc[i][2] = fmaf(a, b.z, acc[i][2]);
            acc[i][3] = fmaf(a, b.w, acc[i][3]);
        }
    }
#pragma unroll
    for (int i = 0; i < 8; i++) {
        int gn = n0g + n0 + i;
        if (gn < NN) {
            float di = g_dinv[gn];
            uint2 o = pack_h4(di * acc[i][0], di * acc[i][1], di * acc[i][2], di * acc[i][3]);
            *(uint2*)&g_hs[(size_t)gn * 64 + c0] = o;
        }
    }
}

// ---------------- gather aggregation : x = relu(dinv_i * (sum_j hs_j + hs_i) + b) ----------------
// 4 nodes per warp (8 lanes each); lane loads uint4 (8 halves); batches of 8 rows pipelined.
__global__ void __launch_bounds__(256) k_gather(const float* __restrict__ bias)
{
    const int lane = threadIdx.x & 31;
    const int warp = threadIdx.x >> 5;
    const int q  = lane >> 3;          // quarter id (node within warp)
    const int ql = lane & 7;           // lane within quarter
    const int node = blockIdx.x * 32 + warp * 4 + q;   // NN divisible by 32

    const int beg = g_rowptr[node], end = g_rowptr[node + 1];

    uint4 self = *(const uint4*)&g_hs[(size_t)node * 64 + ql * 8];
    float2 a0 = __half22float2(*(__half2*)&self.x);
    float2 a1 = __half22float2(*(__half2*)&self.y);
    float2 a2 = __half22float2(*(__half2*)&self.z);
    float2 a3 = __half22float2(*(__half2*)&self.w);

    int p = beg;
    while (true) {
        int rem = end - p;
        int mx = rem;
        mx = max(mx, __shfl_xor_sync(0xffffffffu, mx, 8));
        mx = max(mx, __shfl_xor_sync(0xffffffffu, mx, 16));
        if (mx <= 0) break;
        int cnt = min(8, max(rem, 0));
        int idx = (ql < cnt) ? g_col[p + ql] : 0;

        uint4 v[8];
#pragma unroll
        for (int r = 0; r < 8; r++) {
            int j = __shfl_sync(0xffffffffu, idx, (q << 3) + r);
            v[r] = (r < cnt) ? *(const uint4*)&g_hs[(size_t)j * 64 + ql * 8]
                             : make_uint4(0u, 0u, 0u, 0u);
        }
#pragma unroll
        for (int r = 0; r < 8; r++) {
            float2 v0 = __half22float2(*(__half2*)&v[r].x);
            float2 v1 = __half22float2(*(__half2*)&v[r].y);
            float2 v2 = __half22float2(*(__half2*)&v[r].z);
            float2 v3 = __half22float2(*(__half2*)&v[r].w);
            a0.x += v0.x; a0.y += v0.y;
            a1.x += v1.x; a1.y += v1.y;
            a2.x += v2.x; a2.y += v2.y;
            a3.x += v3.x; a3.y += v3.y;
        }
        p += 8;
    }

    float di = g_dinv[node];
    float4 bA = *(const float4*)&bias[ql * 8];
    float4 bB = *(const float4*)&bias[ql * 8 + 4];
    float4 oA, oB;
    oA.x = fmaxf(fmaf(di, a0.x, bA.x), 0.f);
    oA.y = fmaxf(fmaf(di, a0.y, bA.y), 0.f);
    oA.z = fmaxf(fmaf(di, a1.x, bA.z), 0.f);
    oA.w = fmaxf(fmaf(di, a1.y, bA.w), 0.f);
    oB.x = fmaxf(fmaf(di, a2.x, bB.x), 0.f);
    oB.y = fmaxf(fmaf(di, a2.y, bB.y), 0.f);
    oB.z = fmaxf(fmaf(di, a3.x, bB.z), 0.f);
    oB.w = fmaxf(fmaf(di, a3.y, bB.w), 0.f);
    *(float4*)&g_x[(size_t)node * 64 + ql * 8]     = oA;
    *(float4*)&g_x[(size_t)node * 64 + ql * 8 + 4] = oB;
}

// ---------------- output MLP : out = relu(x @ W1 + b1) @ W2 + b2 ----------------
__global__ void __launch_bounds__(256) k_out(
    const float* __restrict__ W1, const float* __restrict__ B1,
    const float* __restrict__ W2, const float* __restrict__ B2,
    float* __restrict__ out)
{
    __shared__ float W1s[2048];
    __shared__ float W2s[32];
    __shared__ float B1s[32];
    __shared__ float xsh[8][64];
    const int t = threadIdx.x;
    for (int i = t; i < 2048; i += 256) W1s[i] = W1[i];
    if (t < 32) { W2s[t] = W2[t]; B1s[t] = B1[t]; }
    __syncthreads();

    const int lane = t & 31, w = t >> 5;
    const int node = blockIdx.x * 8 + w;
    if (node < NN) {
        xsh[w][lane]      = g_x[(size_t)node * 64 + lane];
        xsh[w][32 + lane] = g_x[(size_t)node * 64 + 32 + lane];
        __syncwarp();
        float m = B1s[lane];
#pragma unroll
        for (int k = 0; k < 64; k++) m = fmaf(xsh[w][k], W1s[k * 32 + lane], m);
        m = fmaxf(m, 0.f) * W2s[lane];
#pragma unroll
        for (int off = 16; off; off >>= 1) m += __shfl_xor_sync(0xffffffffu, m, off);
        if (lane == 0) out[node] = m + B2[0];
    }
}

// ---------------- launch ----------------
extern "C" void kernel_launch(void* const* d_in, const int* in_sizes, int n_in,
                              void* d_out, int out_size)
{
    const float* xf  = (const float*)d_in[0];
    const float* xw  = (const float*)d_in[1];
    const float* xt  = (const float*)d_in[2];
    const void*  ei  = d_in[3];
    const float* wf  = (const float*)d_in[4];
    const float* bf  = (const float*)d_in[5];
    const float* ww  = (const float*)d_in[6];
    const float* bw  = (const float*)d_in[7];
    const float* wt  = (const float*)d_in[8];
    const float* bt  = (const float*)d_in[9];
    const float* w0  = (const float*)d_in[10];
    const float* b0  = (const float*)d_in[11];
    const float* w1  = (const float*)d_in[12];
    const float* b1  = (const float*)d_in[13];
    const float* w2  = (const float*)d_in[14];
    const float* b2  = (const float*)d_in[15];
    const float* ow1 = (const float*)d_in[16];
    const float* ob1 = (const float*)d_in[17];
    const float* ow2 = (const float*)d_in[18];
    const float* ob2 = (const float*)d_in[19];
    float* out = (float*)d_out;

    const int ENC_SMEM = (12288 + 1920 + 192 + 12544 + 2048) * 4;  // 115968 B
    cudaFuncSetAttribute(k_enc0, cudaFuncAttributeMaxDynamicSharedMemorySize, ENC_SMEM);

    const int encTiles = (NN + 63) / 64;    // 1563
    const int linTiles = (NN + 127) / 128;  // 782
    const int gBlocks  = NN / 32;           // 3125
    const int oBlocks  = (NN + 7) / 8;      // 12500
    const int ePairs   = EE / 2;

    // CSR build (by destination) + dinv — single-pass scan puts k_fill at profile slot 3
    k_prep<<<(NN + 255) / 256, 256>>>((const int*)ei);
    k_deg<<<(ePairs + 255) / 256, 256>>>(ei);
    k_scan<<<NBSCAN, 256>>>();
    k_fill<<<(ePairs + 255) / 256, 256>>>(ei);

    // layer 0
    k_enc0<<<encTiles, 256, ENC_SMEM>>>(xf, xw, xt, wf, bf, ww, bw, wt, bt, w0);
    k_gather<<<gBlocks, 256>>>(b0);
    // layer 1
    k_lin<<<linTiles, 256>>>(w1);
    k_gather<<<gBlocks, 256>>>(b1);
    // layer 2
    k_lin<<<linTiles, 256>>>(w2);
    k_gather<<<gBlocks, 256>>>(b2);
    // output MLP
    k_out<<<oBlocks, 256>>>(ow1, ob1, ow2, ob2, out);
}

// round 6
// speedup vs baseline: 1.2328x; 1.0479x over previous
#include <cuda_runtime.h>
#include <cuda_fp16.h>

#define NN 100000
#define EE 3200000
#define HH 64
#define NBSCAN 98

// ---------------- scratch (static device globals; no allocation) ----------------
__device__ int   g_deg[NN];
__device__ int   g_rowptr[NN + 1];
__device__ int   g_cursor[NN];
__device__ int   g_col[EE];
__device__ float g_dinv[NN];
__device__ __align__(16) __half g_hs[NN * HH];   // scaled features for gather (fp16)
__device__ __align__(16) float  g_x[NN * HH];    // layer activations (fp32)
__device__ int   g_is64;
// decoupled-lookback scan state
__device__ volatile int g_bsum[NBSCAN];
__device__ volatile int g_bpre[NBSCAN];
__device__ volatile int g_bflag[NBSCAN];

// packed f32x2 helpers
#define PK2(dst, lo, hi)  asm("mov.b64 %0, {%1, %2};" : "=l"(dst) : "f"(lo), "f"(hi))
#define UPK2(lo, hi, src) asm("mov.b64 {%0, %1}, %2;" : "=f"(lo), "=f"(hi) : "l"(src))
#define FMA2(acc, a, b)   asm("fma.rn.f32x2 %0, %1, %2, %0;" : "+l"(acc) : "l"(a), "l"(b))

// ---------------- prep: zero degrees + scan flags + parallel edge-dtype detect ----------------
__global__ void k_prep(const int* __restrict__ ei32) {
    int i = blockIdx.x * blockDim.x + threadIdx.x;
    if (i < NN) g_deg[i] = 0;
    if (i < NBSCAN) { g_bflag[i] = 0; g_bsum[i] = 0; g_bpre[i] = 0; }
    if (blockIdx.x == 0) {
        __shared__ int cnt;
        if (threadIdx.x == 0) cnt = 0;
        __syncthreads();
        int z = 0;
#pragma unroll
        for (int r = 0; r < 8; r++) {
            int k = 1 + 2 * (threadIdx.x * 8 + r);
            z += (ei32[k] == 0);
        }
#pragma unroll
        for (int o = 16; o; o >>= 1) z += __shfl_xor_sync(0xffffffffu, z, o);
        if ((threadIdx.x & 31) == 0) atomicAdd(&cnt, z);
        __syncthreads();
        if (threadIdx.x == 0) g_is64 = (cnt >= 1536) ? 1 : 0;
    }
}

__device__ __forceinline__ int2 edge_pair(const void* ei, size_t idx2) {
    if (g_is64) {
        longlong2 v = ((const longlong2*)ei)[idx2];
        return make_int2((int)v.x, (int)v.y);
    }
    return ((const int2*)ei)[idx2];
}

// ---------------- CSR build ----------------
__global__ void k_deg(const void* __restrict__ ei) {
    int e2 = blockIdx.x * blockDim.x + threadIdx.x;
    if (e2 < EE / 2) {
        int2 d = edge_pair(ei, (size_t)(EE / 2) + e2);
        atomicAdd(&g_deg[d.x], 1);
        atomicAdd(&g_deg[d.y], 1);
    }
}

// single-pass exclusive scan with decoupled lookback (98 blocks, all resident)
__global__ void __launch_bounds__(256) k_scan() {
    __shared__ int s[256];
    __shared__ int sh_total, sh_exc;
    const int t = threadIdx.x;
    const int bid = blockIdx.x;
    int base = bid * 1024 + t * 4;
    int v[4]; int sum = 0;
#pragma unroll
    for (int r = 0; r < 4; r++) { int i = base + r; v[r] = (i < NN) ? g_deg[i] : 0; sum += v[r]; }
    s[t] = sum;
    __syncthreads();
    for (int off = 1; off < 256; off <<= 1) {
        int x = (t >= off) ? s[t - off] : 0;
        __syncthreads();
        s[t] += x;
        __syncthreads();
    }
    int run = s[t] - sum;
    if (t == 255) {
        sh_total = s[255];
        g_bsum[bid] = s[255];
        __threadfence();
        if (bid == 0) { g_bpre[0] = s[255]; g_bflag[0] = 2; }
        else          { g_bflag[bid] = 1; }
        if (bid == 0) sh_exc = 0;
    }
    __syncthreads();

    if (bid > 0 && t < 32) {
        int lane = t;
        int excl = 0;
        int j = bid - 1;
        while (true) {
            int jj = j - lane;
            int f = 0, val = 0;
            if (jj >= 0) {
                while ((f = g_bflag[jj]) == 0) { }
                val = (f == 2) ? g_bpre[jj] : g_bsum[jj];
            }
            unsigned ball = __ballot_sync(0xffffffffu, (jj >= 0) && (f == 2));
            int contrib;
            if (ball) {
                int l = __ffs(ball) - 1;
                contrib = (lane <= l) ? val : 0;
            } else {
                contrib = (jj >= 0) ? val : 0;
            }
#pragma unroll
            for (int o = 16; o; o >>= 1) contrib += __shfl_xor_sync(0xffffffffu, contrib, o);
            excl += contrib;
            if (ball) break;
            j -= 32;
        }
        if (lane == 0) {
            sh_exc = excl;
            g_bpre[bid] = excl + sh_total;
            __threadfence();
            g_bflag[bid] = 2;
        }
    }
    __syncthreads();

    int exc = sh_exc;
#pragma unroll
    for (int r = 0; r < 4; r++) {
        int i = base + r;
        if (i < NN) {
            int rp = run + exc;
            g_rowptr[i] = rp;
            g_cursor[i] = rp;
            g_dinv[i] = rsqrtf((float)g_deg[i] + 1.0f);
        }
        run += v[r];
    }
    if (bid == 0 && t == 0) g_rowptr[NN] = EE;
}

__global__ void k_fill(const void* __restrict__ ei) {
    int e2 = blockIdx.x * blockDim.x + threadIdx.x;
    if (e2 < EE / 2) {
        int2 s = edge_pair(ei, (size_t)e2);
        int2 d = edge_pair(ei, (size_t)(EE / 2) + e2);
        int p0 = atomicAdd(&g_cursor[d.x], 1);
        g_col[p0] = s.x;
        int p1 = atomicAdd(&g_cursor[d.y], 1);
        g_col[p1] = s.y;
    }
}

// pack float4 -> 4 halves (uint2)
__device__ __forceinline__ uint2 pack_h4(float a, float b, float c, float d) {
    __half2 lo = __floats2half2_rn(a, b);
    __half2 hi = __floats2half2_rn(c, d);
    uint2 r;
    r.x = *(unsigned*)&lo;
    r.y = *(unsigned*)&hi;
    return r;
}

// ---------------- fused encoders + GCN0 linear : hs0 = fp16(dinv .* (relu-concat @ W0)) ----------------
__global__ void __launch_bounds__(256) k_enc0(
    const float* __restrict__ xf, const float* __restrict__ xw, const float* __restrict__ xt,
    const float* __restrict__ wf, const float* __restrict__ bfir,
    const float* __restrict__ ww, const float* __restrict__ bwea,
    const float* __restrict__ wt, const float* __restrict__ bter,
    const float* __restrict__ W0)
{
    extern __shared__ __align__(16) float sm[];
    float* Ws   = sm;            // 192*64 = 12288
    float* Wenc = Ws + 12288;    // 30*64  = 1920
    float* Benc = Wenc + 1920;   // 192
    float* xs   = Benc + 192;    // 64*196 = 12544
    float* raw  = xs + 12544;    // 64*32  = 2048
    const int t = threadIdx.x;

    for (int i = t; i < 12288; i += 256) Ws[i] = W0[i];
    for (int i = t; i < 512;  i += 256) Wenc[i] = wf[i];
    for (int i = t; i < 768;  i += 256) Wenc[512 + i] = ww[i];
    for (int i = t; i < 640;  i += 256) Wenc[1280 + i] = wt[i];
    if (t < 64) { Benc[t] = bfir[t]; Benc[64 + t] = bwea[t]; Benc[128 + t] = bter[t]; }

    const int n0g = blockIdx.x * 64;
    for (int i = t; i < 512; i += 256) { int n = i >> 3, k = i & 7;  int gn = n0g + n; raw[n * 32 + k]      = (gn < NN) ? xf[gn * 8 + k]  : 0.f; }
    for (int i = t; i < 768; i += 256) { int n = i / 12, k = i % 12; int gn = n0g + n; raw[n * 32 + 8 + k]  = (gn < NN) ? xw[gn * 12 + k] : 0.f; }
    for (int i = t; i < 640; i += 256) { int n = i / 10, k = i % 10; int gn = n0g + n; raw[n * 32 + 20 + k] = (gn < NN) ? xt[gn * 10 + k] : 0.f; }
    __syncthreads();

    for (int i = t; i < 12288; i += 256) {
        int n = i / 192, c = i % 192;
        int mod = c >> 6, cc = c & 63;
        int koff = (mod == 0) ? 0 : ((mod == 1) ? 8 : 20);
        int kn   = (mod == 0) ? 8 : ((mod == 1) ? 12 : 10);
        const float* wr = Wenc + ((mod == 0) ? 0 : ((mod == 1) ? 512 : 1280));
        float v = Benc[c];
        for (int k = 0; k < kn; k++) v = fmaf(raw[n * 32 + koff + k], wr[k * 64 + cc], v);
        xs[n * 196 + c] = fmaxf(v, 0.f);
    }
    __syncthreads();

    // stage B: 64x64 tile, 4x4 micro-tile, packed f32x2 FMA
    const int cg = t & 15, ng = t >> 4;
    const int n0 = ng * 4, c0 = cg * 4;
    unsigned long long acc01[4] = {0, 0, 0, 0}, acc23[4] = {0, 0, 0, 0};

#pragma unroll 4
    for (int k = 0; k < 192; k++) {
        float4 b = *(const float4*)&Ws[k * 64 + c0];
        unsigned long long b01, b23;
        PK2(b01, b.x, b.y);
        PK2(b23, b.z, b.w);
#pragma unroll
        for (int i = 0; i < 4; i++) {
            float a = xs[(n0 + i) * 196 + k];
            unsigned long long aa;
            PK2(aa, a, a);
            FMA2(acc01[i], aa, b01);
            FMA2(acc23[i], aa, b23);
        }
    }
#pragma unroll
    for (int i = 0; i < 4; i++) {
        int gn = n0g + n0 + i;
        if (gn < NN) {
            float di = g_dinv[gn];
            float a0, a1, a2, a3;
            UPK2(a0, a1, acc01[i]);
            UPK2(a2, a3, acc23[i]);
            uint2 o = pack_h4(di * a0, di * a1, di * a2, di * a3);
            *(uint2*)&g_hs[(size_t)gn * 64 + c0] = o;
        }
    }
}

// ---------------- GCN linear : hs = fp16(dinv .* (x @ W)) , packed f32x2 FMA ----------------
__global__ void __launch_bounds__(256) k_lin(const float* __restrict__ W)
{
    __shared__ __align__(16) float Ws[4096];
    __shared__ __align__(16) float xs[128 * 68];
    const int t = threadIdx.x;
    for (int i = t; i < 4096; i += 256) Ws[i] = W[i];

    const int n0g = blockIdx.x * 128;
    for (int i = t; i < 2048; i += 256) {
        int n = i >> 4, k4 = i & 15;
        int gn = n0g + n;
        float4 v = (gn < NN) ? *(const float4*)&g_x[(size_t)gn * 64 + k4 * 4] : make_float4(0, 0, 0, 0);
        *(float4*)&xs[n * 68 + k4 * 4] = v;
    }
    __syncthreads();

    const int cg = t & 15, rg = t >> 4;
    const int n0 = rg * 8, c0 = cg * 4;
    unsigned long long acc01[8], acc23[8];
#pragma unroll
    for (int i = 0; i < 8; i++) { acc01[i] = 0; acc23[i] = 0; }

#pragma unroll 4
    for (int k = 0; k < 64; k++) {
        float4 b = *(const float4*)&Ws[k * 64 + c0];
        unsigned long long b01, b23;
        PK2(b01, b.x, b.y);
        PK2(b23, b.z, b.w);
#pragma unroll
        for (int i = 0; i < 8; i++) {
            float a = xs[(n0 + i) * 68 + k];
            unsigned long long aa;
            PK2(aa, a, a);
            FMA2(acc01[i], aa, b01);
            FMA2(acc23[i], aa, b23);
        }
    }
#pragma unroll
    for (int i = 0; i < 8; i++) {
        int gn = n0g + n0 + i;
        if (gn < NN) {
            float di = g_dinv[gn];
            float a0, a1, a2, a3;
            UPK2(a0, a1, acc01[i]);
            UPK2(a2, a3, acc23[i]);
            uint2 o = pack_h4(di * a0, di * a1, di * a2, di * a3);
            *(uint2*)&g_hs[(size_t)gn * 64 + c0] = o;
        }
    }
}

// ---------------- gather aggregation : x = relu(dinv_i * (sum_j hs_j + hs_i) + b) ----------------
__global__ void __launch_bounds__(256) k_gather(const float* __restrict__ bias)
{
    const int lane = threadIdx.x & 31;
    const int warp = threadIdx.x >> 5;
    const int q  = lane >> 3;
    const int ql = lane & 7;
    const int node = blockIdx.x * 32 + warp * 4 + q;

    const int beg = g_rowptr[node], end = g_rowptr[node + 1];

    uint4 self = *(const uint4*)&g_hs[(size_t)node * 64 + ql * 8];
    float2 a0 = __half22float2(*(__half2*)&self.x);
    float2 a1 = __half22float2(*(__half2*)&self.y);
    float2 a2 = __half22float2(*(__half2*)&self.z);
    float2 a3 = __half22float2(*(__half2*)&self.w);

    int p = beg;
    while (true) {
        int rem = end - p;
        int mx = rem;
        mx = max(mx, __shfl_xor_sync(0xffffffffu, mx, 8));
        mx = max(mx, __shfl_xor_sync(0xffffffffu, mx, 16));
        if (mx <= 0) break;
        int cnt = min(8, max(rem, 0));
        int idx = (ql < cnt) ? g_col[p + ql] : 0;

        uint4 v[8];
#pragma unroll
        for (int r = 0; r < 8; r++) {
            int j = __shfl_sync(0xffffffffu, idx, (q << 3) + r);
            v[r] = (r < cnt) ? *(const uint4*)&g_hs[(size_t)j * 64 + ql * 8]
                             : make_uint4(0u, 0u, 0u, 0u);
        }
#pragma unroll
        for (int r = 0; r < 8; r++) {
            float2 v0 = __half22float2(*(__half2*)&v[r].x);
            float2 v1 = __half22float2(*(__half2*)&v[r].y);
            float2 v2 = __half22float2(*(__half2*)&v[r].z);
            float2 v3 = __half22float2(*(__half2*)&v[r].w);
            a0.x += v0.x; a0.y += v0.y;
            a1.x += v1.x; a1.y += v1.y;
            a2.x += v2.x; a2.y += v2.y;
            a3.x += v3.x; a3.y += v3.y;
        }
        p += 8;
    }

    float di = g_dinv[node];
    float4 bA = *(const float4*)&bias[ql * 8];
    float4 bB = *(const float4*)&bias[ql * 8 + 4];
    float4 oA, oB;
    oA.x = fmaxf(fmaf(di, a0.x, bA.x), 0.f);
    oA.y = fmaxf(fmaf(di, a0.y, bA.y), 0.f);
    oA.z = fmaxf(fmaf(di, a1.x, bA.z), 0.f);
    oA.w = fmaxf(fmaf(di, a1.y, bA.w), 0.f);
    oB.x = fmaxf(fmaf(di, a2.x, bB.x), 0.f);
    oB.y = fmaxf(fmaf(di, a2.y, bB.y), 0.f);
    oB.z = fmaxf(fmaf(di, a3.x, bB.z), 0.f);
    oB.w = fmaxf(fmaf(di, a3.y, bB.w), 0.f);
    *(float4*)&g_x[(size_t)node * 64 + ql * 8]     = oA;
    *(float4*)&g_x[(size_t)node * 64 + ql * 8 + 4] = oB;
}

// ---------------- output MLP : out = relu(x @ W1 + b1) @ W2 + b2 (128 nodes/block) ----------------
__global__ void __launch_bounds__(256) k_out(
    const float* __restrict__ W1, const float* __restrict__ B1,
    const float* __restrict__ W2, const float* __restrict__ B2,
    float* __restrict__ out)
{
    __shared__ float W1s[2048];
    __shared__ float W2s[32];
    __shared__ float B1s[32];
    __shared__ float xsh[8][64];
    const int t = threadIdx.x;
    for (int i = t; i < 2048; i += 256) W1s[i] = W1[i];
    if (t < 32) { W2s[t] = W2[t]; B1s[t] = B1[t]; }
    __syncthreads();

    const int lane = t & 31, w = t >> 5;
#pragma unroll 1
    for (int it = 0; it < 16; it++) {
        const int node = blockIdx.x * 128 + it * 8 + w;
        if (node < NN) {
            xsh[w][lane]      = g_x[(size_t)node * 64 + lane];
            xsh[w][32 + lane] = g_x[(size_t)node * 64 + 32 + lane];
            __syncwarp();
            float m = B1s[lane];
#pragma unroll
            for (int k = 0; k < 64; k++) m = fmaf(xsh[w][k], W1s[k * 32 + lane], m);
            m = fmaxf(m, 0.f) * W2s[lane];
#pragma unroll
            for (int off = 16; off; off >>= 1) m += __shfl_xor_sync(0xffffffffu, m, off);
            if (lane == 0) out[node] = m + B2[0];
            __syncwarp();
        }
    }
}

// ---------------- launch ----------------
extern "C" void kernel_launch(void* const* d_in, const int* in_sizes, int n_in,
                              void* d_out, int out_size)
{
    const float* xf  = (const float*)d_in[0];
    const float* xw  = (const float*)d_in[1];
    const float* xt  = (const float*)d_in[2];
    const void*  ei  = d_in[3];
    const float* wf  = (const float*)d_in[4];
    const float* bf  = (const float*)d_in[5];
    const float* ww  = (const float*)d_in[6];
    const float* bw  = (const float*)d_in[7];
    const float* wt  = (const float*)d_in[8];
    const float* bt  = (const float*)d_in[9];
    const float* w0  = (const float*)d_in[10];
    const float* b0  = (const float*)d_in[11];
    const float* w1  = (const float*)d_in[12];
    const float* b1  = (const float*)d_in[13];
    const float* w2  = (const float*)d_in[14];
    const float* b2  = (const float*)d_in[15];
    const float* ow1 = (const float*)d_in[16];
    const float* ob1 = (const float*)d_in[17];
    const float* ow2 = (const float*)d_in[18];
    const float* ob2 = (const float*)d_in[19];
    float* out = (float*)d_out;

    const int ENC_SMEM = (12288 + 1920 + 192 + 12544 + 2048) * 4;  // 115968 B
    cudaFuncSetAttribute(k_enc0, cudaFuncAttributeMaxDynamicSharedMemorySize, ENC_SMEM);

    const int encTiles = (NN + 63) / 64;     // 1563
    const int linTiles = (NN + 127) / 128;   // 782
    const int gBlocks  = NN / 32;            // 3125
    const int oBlocks  = (NN + 127) / 128;   // 782
    const int ePairs   = EE / 2;

    // CSR build; enc0 moved before fill so the fixed ncu capture slot lands on enc0
    k_prep<<<(NN + 255) / 256, 256>>>((const int*)ei);
    k_deg<<<(ePairs + 255) / 256, 256>>>(ei);
    k_scan<<<NBSCAN, 256>>>();
    k_enc0<<<encTiles, 256, ENC_SMEM>>>(xf, xw, xt, wf, bf, ww, bw, wt, bt, w0);  // slot 3
    k_fill<<<(ePairs + 255) / 256, 256>>>(ei);

    // layer 0 gather
    k_gather<<<gBlocks, 256>>>(b0);
    // layer 1
    k_lin<<<linTiles, 256>>>(w1);
    k_gather<<<gBlocks, 256>>>(b1);
    // layer 2
    k_lin<<<linTiles, 256>>>(w2);
    k_gather<<<gBlocks, 256>>>(b2);
    // output MLP
    k_out<<<oBlocks, 256>>>(ow1, ob1, ow2, ob2, out);
}

// round 7
// speedup vs baseline: 1.2929x; 1.0488x over previous
#include <cuda_runtime.h>
#include <cuda_fp16.h>

#define NN 100000
#define EE 3200000
#define HH 64
#define NBSCAN 98

// ---------------- scratch (static device globals; no allocation) ----------------
__device__ int   g_deg[NN];
__device__ int   g_rowptr[NN + 1];
__device__ int   g_cursor[NN];
__device__ int   g_col[EE];
__device__ float g_dinv[NN];
__device__ __align__(16) __half g_hs[NN * HH];   // scaled features for gather (fp16)
__device__ __align__(16) float  g_x[NN * HH];    // layer activations (fp32)
__device__ int   g_is64;
// decoupled-lookback scan state
__device__ volatile int g_bsum[NBSCAN];
__device__ volatile int g_bpre[NBSCAN];
__device__ volatile int g_bflag[NBSCAN];

// packed f32x2 helpers
#define PK2(dst, lo, hi)  asm("mov.b64 %0, {%1, %2};" : "=l"(dst) : "f"(lo), "f"(hi))
#define UPK2(lo, hi, src) asm("mov.b64 {%0, %1}, %2;" : "=f"(lo), "=f"(hi) : "l"(src))
#define FMA2(acc, a, b)   asm("fma.rn.f32x2 %0, %1, %2, %0;" : "+l"(acc) : "l"(a), "l"(b))

// ---------------- prep: zero degrees + scan flags + parallel edge-dtype detect ----------------
__global__ void k_prep(const int* __restrict__ ei32) {
    int i = blockIdx.x * blockDim.x + threadIdx.x;
    if (i < NN) g_deg[i] = 0;
    if (i < NBSCAN) { g_bflag[i] = 0; g_bsum[i] = 0; g_bpre[i] = 0; }
    if (blockIdx.x == 0) {
        __shared__ int cnt;
        if (threadIdx.x == 0) cnt = 0;
        __syncthreads();
        int z = 0;
#pragma unroll
        for (int r = 0; r < 8; r++) {
            int k = 1 + 2 * (threadIdx.x * 8 + r);
            z += (ei32[k] == 0);
        }
#pragma unroll
        for (int o = 16; o; o >>= 1) z += __shfl_xor_sync(0xffffffffu, z, o);
        if ((threadIdx.x & 31) == 0) atomicAdd(&cnt, z);
        __syncthreads();
        if (threadIdx.x == 0) g_is64 = (cnt >= 1536) ? 1 : 0;
    }
}

__device__ __forceinline__ int2 edge_pair(const void* ei, size_t idx2) {
    if (g_is64) {
        longlong2 v = ((const longlong2*)ei)[idx2];
        return make_int2((int)v.x, (int)v.y);
    }
    return ((const int2*)ei)[idx2];
}

// ---------------- CSR build ----------------
__global__ void k_deg(const void* __restrict__ ei) {
    int e2 = blockIdx.x * blockDim.x + threadIdx.x;
    if (e2 < EE / 2) {
        int2 d = edge_pair(ei, (size_t)(EE / 2) + e2);
        atomicAdd(&g_deg[d.x], 1);
        atomicAdd(&g_deg[d.y], 1);
    }
}

// single-pass exclusive scan with decoupled lookback (98 blocks, all resident)
__global__ void __launch_bounds__(256) k_scan() {
    __shared__ int s[256];
    __shared__ int sh_total, sh_exc;
    const int t = threadIdx.x;
    const int bid = blockIdx.x;
    int base = bid * 1024 + t * 4;
    int v[4]; int sum = 0;
#pragma unroll
    for (int r = 0; r < 4; r++) { int i = base + r; v[r] = (i < NN) ? g_deg[i] : 0; sum += v[r]; }
    s[t] = sum;
    __syncthreads();
    for (int off = 1; off < 256; off <<= 1) {
        int x = (t >= off) ? s[t - off] : 0;
        __syncthreads();
        s[t] += x;
        __syncthreads();
    }
    int run = s[t] - sum;
    if (t == 255) {
        sh_total = s[255];
        g_bsum[bid] = s[255];
        __threadfence();
        if (bid == 0) { g_bpre[0] = s[255]; g_bflag[0] = 2; }
        else          { g_bflag[bid] = 1; }
        if (bid == 0) sh_exc = 0;
    }
    __syncthreads();

    if (bid > 0 && t < 32) {
        int lane = t;
        int excl = 0;
        int j = bid - 1;
        while (true) {
            int jj = j - lane;
            int f = 0, val = 0;
            if (jj >= 0) {
                while ((f = g_bflag[jj]) == 0) { }
                val = (f == 2) ? g_bpre[jj] : g_bsum[jj];
            }
            unsigned ball = __ballot_sync(0xffffffffu, (jj >= 0) && (f == 2));
            int contrib;
            if (ball) {
                int l = __ffs(ball) - 1;
                contrib = (lane <= l) ? val : 0;
            } else {
                contrib = (jj >= 0) ? val : 0;
            }
#pragma unroll
            for (int o = 16; o; o >>= 1) contrib += __shfl_xor_sync(0xffffffffu, contrib, o);
            excl += contrib;
            if (ball) break;
            j -= 32;
        }
        if (lane == 0) {
            sh_exc = excl;
            g_bpre[bid] = excl + sh_total;
            __threadfence();
            g_bflag[bid] = 2;
        }
    }
    __syncthreads();

    int exc = sh_exc;
#pragma unroll
    for (int r = 0; r < 4; r++) {
        int i = base + r;
        if (i < NN) {
            int rp = run + exc;
            g_rowptr[i] = rp;
            g_cursor[i] = rp;
            g_dinv[i] = rsqrtf((float)g_deg[i] + 1.0f);
        }
        run += v[r];
    }
    if (bid == 0 && t == 0) g_rowptr[NN] = EE;
}

__global__ void k_fill(const void* __restrict__ ei) {
    int e2 = blockIdx.x * blockDim.x + threadIdx.x;
    if (e2 < EE / 2) {
        int2 s = edge_pair(ei, (size_t)e2);
        int2 d = edge_pair(ei, (size_t)(EE / 2) + e2);
        int p0 = atomicAdd(&g_cursor[d.x], 1);
        g_col[p0] = s.x;
        int p1 = atomicAdd(&g_cursor[d.y], 1);
        g_col[p1] = s.y;
    }
}

// pack float4 -> 4 halves (uint2)
__device__ __forceinline__ uint2 pack_h4(float a, float b, float c, float d) {
    __half2 lo = __floats2half2_rn(a, b);
    __half2 hi = __floats2half2_rn(c, d);
    uint2 r;
    r.x = *(unsigned*)&lo;
    r.y = *(unsigned*)&hi;
    return r;
}

// ---------------- fused encoders + GCN0 linear : hs0 = fp16(dinv .* (relu-concat @ W0)) ----------------
// 512 threads, 64-node tile: 16 warps/SM to cover LDS+FMA latency (was 8 @ 12.5% occ).
__global__ void __launch_bounds__(512) k_enc0(
    const float* __restrict__ xf, const float* __restrict__ xw, const float* __restrict__ xt,
    const float* __restrict__ wf, const float* __restrict__ bfir,
    const float* __restrict__ ww, const float* __restrict__ bwea,
    const float* __restrict__ wt, const float* __restrict__ bter,
    const float* __restrict__ W0)
{
    extern __shared__ __align__(16) float sm[];
    float* Ws   = sm;            // 192*64 = 12288
    float* Wenc = Ws + 12288;    // 30*64  = 1920
    float* Benc = Wenc + 1920;   // 192
    float* xs   = Benc + 192;    // 64*196 = 12544
    float* raw  = xs + 12544;    // 64*32  = 2048
    const int t = threadIdx.x;

    for (int i = t; i < 12288; i += 512) Ws[i] = W0[i];
    for (int i = t; i < 512;  i += 512) Wenc[i] = wf[i];
    for (int i = t; i < 768;  i += 512) Wenc[512 + i] = ww[i];
    for (int i = t; i < 640;  i += 512) Wenc[1280 + i] = wt[i];
    if (t < 64) { Benc[t] = bfir[t]; Benc[64 + t] = bwea[t]; Benc[128 + t] = bter[t]; }

    const int n0g = blockIdx.x * 64;
    for (int i = t; i < 512; i += 512) { int n = i >> 3, k = i & 7;  int gn = n0g + n; raw[n * 32 + k]      = (gn < NN) ? xf[gn * 8 + k]  : 0.f; }
    for (int i = t; i < 768; i += 512) { int n = i / 12, k = i % 12; int gn = n0g + n; raw[n * 32 + 8 + k]  = (gn < NN) ? xw[gn * 12 + k] : 0.f; }
    for (int i = t; i < 640; i += 512) { int n = i / 10, k = i % 10; int gn = n0g + n; raw[n * 32 + 20 + k] = (gn < NN) ? xt[gn * 10 + k] : 0.f; }
    __syncthreads();

    for (int i = t; i < 12288; i += 512) {
        int n = i / 192, c = i % 192;
        int mod = c >> 6, cc = c & 63;
        int koff = (mod == 0) ? 0 : ((mod == 1) ? 8 : 20);
        int kn   = (mod == 0) ? 8 : ((mod == 1) ? 12 : 10);
        const float* wr = Wenc + ((mod == 0) ? 0 : ((mod == 1) ? 512 : 1280));
        float v = Benc[c];
        for (int k = 0; k < kn; k++) v = fmaf(raw[n * 32 + koff + k], wr[k * 64 + cc], v);
        xs[n * 196 + c] = fmaxf(v, 0.f);
    }
    __syncthreads();

    // stage B: 64x64 tile, 2x4 micro-tile per thread (512 threads), packed f32x2 FMA
    const int cg = t & 15, rg = t >> 4;     // rg: 0..31
    const int n0 = rg * 2, c0 = cg * 4;
    unsigned long long acc01[2] = {0, 0}, acc23[2] = {0, 0};

#pragma unroll 4
    for (int k = 0; k < 192; k++) {
        float4 b = *(const float4*)&Ws[k * 64 + c0];
        unsigned long long b01, b23;
        PK2(b01, b.x, b.y);
        PK2(b23, b.z, b.w);
#pragma unroll
        for (int i = 0; i < 2; i++) {
            float a = xs[(n0 + i) * 196 + k];
            unsigned long long aa;
            PK2(aa, a, a);
            FMA2(acc01[i], aa, b01);
            FMA2(acc23[i], aa, b23);
        }
    }
#pragma unroll
    for (int i = 0; i < 2; i++) {
        int gn = n0g + n0 + i;
        if (gn < NN) {
            float di = g_dinv[gn];
            float a0, a1, a2, a3;
            UPK2(a0, a1, acc01[i]);
            UPK2(a2, a3, acc23[i]);
            uint2 o = pack_h4(di * a0, di * a1, di * a2, di * a3);
            *(uint2*)&g_hs[(size_t)gn * 64 + c0] = o;
        }
    }
}

// ---------------- GCN linear : hs = fp16(dinv .* (x @ W)) , packed f32x2 FMA ----------------
__global__ void __launch_bounds__(256) k_lin(const float* __restrict__ W)
{
    __shared__ __align__(16) float Ws[4096];
    __shared__ __align__(16) float xs[128 * 68];
    const int t = threadIdx.x;
    for (int i = t; i < 4096; i += 256) Ws[i] = W[i];

    const int n0g = blockIdx.x * 128;
    for (int i = t; i < 2048; i += 256) {
        int n = i >> 4, k4 = i & 15;
        int gn = n0g + n;
        float4 v = (gn < NN) ? *(const float4*)&g_x[(size_t)gn * 64 + k4 * 4] : make_float4(0, 0, 0, 0);
        *(float4*)&xs[n * 68 + k4 * 4] = v;
    }
    __syncthreads();

    const int cg = t & 15, rg = t >> 4;
    const int n0 = rg * 8, c0 = cg * 4;
    unsigned long long acc01[8], acc23[8];
#pragma unroll
    for (int i = 0; i < 8; i++) { acc01[i] = 0; acc23[i] = 0; }

#pragma unroll 4
    for (int k = 0; k < 64; k++) {
        float4 b = *(const float4*)&Ws[k * 64 + c0];
        unsigned long long b01, b23;
        PK2(b01, b.x, b.y);
        PK2(b23, b.z, b.w);
#pragma unroll
        for (int i = 0; i < 8; i++) {
            float a = xs[(n0 + i) * 68 + k];
            unsigned long long aa;
            PK2(aa, a, a);
            FMA2(acc01[i], aa, b01);
            FMA2(acc23[i], aa, b23);
        }
    }
#pragma unroll
    for (int i = 0; i < 8; i++) {
        int gn = n0g + n0 + i;
        if (gn < NN) {
            float di = g_dinv[gn];
            float a0, a1, a2, a3;
            UPK2(a0, a1, acc01[i]);
            UPK2(a2, a3, acc23[i]);
            uint2 o = pack_h4(di * a0, di * a1, di * a2, di * a3);
            *(uint2*)&g_hs[(size_t)gn * 64 + c0] = o;
        }
    }
}

// ---------------- gather aggregation : x = relu(dinv_i * (sum_j hs_j + hs_i) + b) ----------------
__global__ void __launch_bounds__(256) k_gather(const float* __restrict__ bias)
{
    const int lane = threadIdx.x & 31;
    const int warp = threadIdx.x >> 5;
    const int q  = lane >> 3;
    const int ql = lane & 7;
    const int node = blockIdx.x * 32 + warp * 4 + q;

    const int beg = g_rowptr[node], end = g_rowptr[node + 1];

    uint4 self = *(const uint4*)&g_hs[(size_t)node * 64 + ql * 8];
    float2 a0 = __half22float2(*(__half2*)&self.x);
    float2 a1 = __half22float2(*(__half2*)&self.y);
    float2 a2 = __half22float2(*(__half2*)&self.z);
    float2 a3 = __half22float2(*(__half2*)&self.w);

    int p = beg;
    while (true) {
        int rem = end - p;
        int mx = rem;
        mx = max(mx, __shfl_xor_sync(0xffffffffu, mx, 8));
        mx = max(mx, __shfl_xor_sync(0xffffffffu, mx, 16));
        if (mx <= 0) break;
        int cnt = min(8, max(rem, 0));
        int idx = (ql < cnt) ? g_col[p + ql] : 0;

        uint4 v[8];
#pragma unroll
        for (int r = 0; r < 8; r++) {
            int j = __shfl_sync(0xffffffffu, idx, (q << 3) + r);
            v[r] = (r < cnt) ? *(const uint4*)&g_hs[(size_t)j * 64 + ql * 8]
                             : make_uint4(0u, 0u, 0u, 0u);
        }
#pragma unroll
        for (int r = 0; r < 8; r++) {
            float2 v0 = __half22float2(*(__half2*)&v[r].x);
            float2 v1 = __half22float2(*(__half2*)&v[r].y);
            float2 v2 = __half22float2(*(__half2*)&v[r].z);
            float2 v3 = __half22float2(*(__half2*)&v[r].w);
            a0.x += v0.x; a0.y += v0.y;
            a1.x += v1.x; a1.y += v1.y;
            a2.x += v2.x; a2.y += v2.y;
            a3.x += v3.x; a3.y += v3.y;
        }
        p += 8;
    }

    float di = g_dinv[node];
    float4 bA = *(const float4*)&bias[ql * 8];
    float4 bB = *(const float4*)&bias[ql * 8 + 4];
    float4 oA, oB;
    oA.x = fmaxf(fmaf(di, a0.x, bA.x), 0.f);
    oA.y = fmaxf(fmaf(di, a0.y, bA.y), 0.f);
    oA.z = fmaxf(fmaf(di, a1.x, bA.z), 0.f);
    oA.w = fmaxf(fmaf(di, a1.y, bA.w), 0.f);
    oB.x = fmaxf(fmaf(di, a2.x, bB.x), 0.f);
    oB.y = fmaxf(fmaf(di, a2.y, bB.y), 0.f);
    oB.z = fmaxf(fmaf(di, a3.x, bB.z), 0.f);
    oB.w = fmaxf(fmaf(di, a3.y, bB.w), 0.f);
    *(float4*)&g_x[(size_t)node * 64 + ql * 8]     = oA;
    *(float4*)&g_x[(size_t)node * 64 + ql * 8 + 4] = oB;
}

// ---------------- output MLP : out = relu(x @ W1 + b1) @ W2 + b2 (128 nodes/block) ----------------
__global__ void __launch_bounds__(256) k_out(
    const float* __restrict__ W1, const float* __restrict__ B1,
    const float* __restrict__ W2, const float* __restrict__ B2,
    float* __restrict__ out)
{
    __shared__ float W1s[2048];
    __shared__ float W2s[32];
    __shared__ float B1s[32];
    __shared__ float xsh[8][64];
    const int t = threadIdx.x;
    for (int i = t; i < 2048; i += 256) W1s[i] = W1[i];
    if (t < 32) { W2s[t] = W2[t]; B1s[t] = B1[t]; }
    __syncthreads();

    const int lane = t & 31, w = t >> 5;
#pragma unroll 1
    for (int it = 0; it < 16; it++) {
        const int node = blockIdx.x * 128 + it * 8 + w;
        if (node < NN) {
            xsh[w][lane]      = g_x[(size_t)node * 64 + lane];
            xsh[w][32 + lane] = g_x[(size_t)node * 64 + 32 + lane];
            __syncwarp();
            float m = B1s[lane];
#pragma unroll
            for (int k = 0; k < 64; k++) m = fmaf(xsh[w][k], W1s[k * 32 + lane], m);
            m = fmaxf(m, 0.f) * W2s[lane];
#pragma unroll
            for (int off = 16; off; off >>= 1) m += __shfl_xor_sync(0xffffffffu, m, off);
            if (lane == 0) out[node] = m + B2[0];
            __syncwarp();
        }
    }
}

// ---------------- launch ----------------
extern "C" void kernel_launch(void* const* d_in, const int* in_sizes, int n_in,
                              void* d_out, int out_size)
{
    const float* xf  = (const float*)d_in[0];
    const float* xw  = (const float*)d_in[1];
    const float* xt  = (const float*)d_in[2];
    const void*  ei  = d_in[3];
    const float* wf  = (const float*)d_in[4];
    const float* bf  = (const float*)d_in[5];
    const float* ww  = (const float*)d_in[6];
    const float* bw  = (const float*)d_in[7];
    const float* wt  = (const float*)d_in[8];
    const float* bt  = (const float*)d_in[9];
    const float* w0  = (const float*)d_in[10];
    const float* b0  = (const float*)d_in[11];
    const float* w1  = (const float*)d_in[12];
    const float* b1  = (const float*)d_in[13];
    const float* w2  = (const float*)d_in[14];
    const float* b2  = (const float*)d_in[15];
    const float* ow1 = (const float*)d_in[16];
    const float* ob1 = (const float*)d_in[17];
    const float* ow2 = (const float*)d_in[18];
    const float* ob2 = (const float*)d_in[19];
    float* out = (float*)d_out;

    const int ENC_SMEM = (12288 + 1920 + 192 + 12544 + 2048) * 4;  // 115968 B
    cudaFuncSetAttribute(k_enc0, cudaFuncAttributeMaxDynamicSharedMemorySize, ENC_SMEM);

    const int encTiles = (NN + 63) / 64;     // 1563
    const int linTiles = (NN + 127) / 128;   // 782
    const int gBlocks  = NN / 32;            // 3125
    const int oBlocks  = (NN + 127) / 128;   // 782
    const int ePairs   = EE / 2;

    // CSR build; enc0 kept at ncu capture slot 3 to verify the occupancy fix
    k_prep<<<(NN + 255) / 256, 256>>>((const int*)ei);
    k_deg<<<(ePairs + 255) / 256, 256>>>(ei);
    k_scan<<<NBSCAN, 256>>>();
    k_enc0<<<encTiles, 512, ENC_SMEM>>>(xf, xw, xt, wf, bf, ww, bw, wt, bt, w0);  // slot 3
    k_fill<<<(ePairs + 255) / 256, 256>>>(ei);

    // layer 0 gather
    k_gather<<<gBlocks, 256>>>(b0);
    // layer 1
    k_lin<<<linTiles, 256>>>(w1);
    k_gather<<<gBlocks, 256>>>(b1);
    // layer 2
    k_lin<<<linTiles, 256>>>(w2);
    k_gather<<<gBlocks, 256>>>(b2);
    // output MLP
    k_out<<<oBlocks, 256>>>(ow1, ob1, ow2, ob2, out);
}

// round 8
// speedup vs baseline: 1.4034x; 1.0855x over previous
#include <cuda_runtime.h>
#include <cuda_fp16.h>

#define NN 100000
#define EE 3200000
#define HH 64
#define NBSCAN 98

// ---------------- scratch (static device globals; no allocation) ----------------
__device__ int   g_deg[NN];
__device__ int   g_rowptr[NN + 1];
__device__ int   g_cursor[NN];
__device__ int   g_col[EE];
__device__ float g_dinv[NN];
__device__ __align__(16) __half g_hs[NN * HH];   // scaled features for gather (fp16)
__device__ __align__(16) float  g_x[NN * HH];    // layer activations (fp32)
__device__ int   g_is64;
// decoupled-lookback scan state
__device__ volatile int g_bsum[NBSCAN];
__device__ volatile int g_bpre[NBSCAN];
__device__ volatile int g_bflag[NBSCAN];

// packed f32x2 helpers
#define PK2(dst, lo, hi)  asm("mov.b64 %0, {%1, %2};" : "=l"(dst) : "f"(lo), "f"(hi))
#define UPK2(lo, hi, src) asm("mov.b64 {%0, %1}, %2;" : "=f"(lo), "=f"(hi) : "l"(src))
#define FMA2(acc, a, b)   asm("fma.rn.f32x2 %0, %1, %2, %0;" : "+l"(acc) : "l"(a), "l"(b))

// ---------------- prep: zero degrees + scan flags + parallel edge-dtype detect ----------------
__global__ void k_prep(const int* __restrict__ ei32) {
    int i = blockIdx.x * blockDim.x + threadIdx.x;
    if (i < NN) g_deg[i] = 0;
    if (i < NBSCAN) { g_bflag[i] = 0; g_bsum[i] = 0; g_bpre[i] = 0; }
    if (blockIdx.x == 0) {
        __shared__ int cnt;
        if (threadIdx.x == 0) cnt = 0;
        __syncthreads();
        int z = 0;
#pragma unroll
        for (int r = 0; r < 8; r++) {
            int k = 1 + 2 * (threadIdx.x * 8 + r);
            z += (ei32[k] == 0);
        }
#pragma unroll
        for (int o = 16; o; o >>= 1) z += __shfl_xor_sync(0xffffffffu, z, o);
        if ((threadIdx.x & 31) == 0) atomicAdd(&cnt, z);
        __syncthreads();
        if (threadIdx.x == 0) g_is64 = (cnt >= 1536) ? 1 : 0;
    }
}

__device__ __forceinline__ int2 edge_pair(const void* ei, size_t idx2) {
    if (g_is64) {
        longlong2 v = ((const longlong2*)ei)[idx2];
        return make_int2((int)v.x, (int)v.y);
    }
    return ((const int2*)ei)[idx2];
}

// ---------------- CSR build ----------------
__global__ void k_deg(const void* __restrict__ ei) {
    int e2 = blockIdx.x * blockDim.x + threadIdx.x;
    if (e2 < EE / 2) {
        int2 d = edge_pair(ei, (size_t)(EE / 2) + e2);
        atomicAdd(&g_deg[d.x], 1);
        atomicAdd(&g_deg[d.y], 1);
    }
}

// single-pass exclusive scan with decoupled lookback (98 blocks, all resident)
__global__ void __launch_bounds__(256) k_scan() {
    __shared__ int s[256];
    __shared__ int sh_total, sh_exc;
    const int t = threadIdx.x;
    const int bid = blockIdx.x;
    int base = bid * 1024 + t * 4;
    int v[4]; int sum = 0;
#pragma unroll
    for (int r = 0; r < 4; r++) { int i = base + r; v[r] = (i < NN) ? g_deg[i] : 0; sum += v[r]; }
    s[t] = sum;
    __syncthreads();
    for (int off = 1; off < 256; off <<= 1) {
        int x = (t >= off) ? s[t - off] : 0;
        __syncthreads();
        s[t] += x;
        __syncthreads();
    }
    int run = s[t] - sum;
    if (t == 255) {
        sh_total = s[255];
        g_bsum[bid] = s[255];
        __threadfence();
        if (bid == 0) { g_bpre[0] = s[255]; g_bflag[0] = 2; }
        else          { g_bflag[bid] = 1; }
        if (bid == 0) sh_exc = 0;
    }
    __syncthreads();

    if (bid > 0 && t < 32) {
        int lane = t;
        int excl = 0;
        int j = bid - 1;
        while (true) {
            int jj = j - lane;
            int f = 0, val = 0;
            if (jj >= 0) {
                while ((f = g_bflag[jj]) == 0) { }
                val = (f == 2) ? g_bpre[jj] : g_bsum[jj];
            }
            unsigned ball = __ballot_sync(0xffffffffu, (jj >= 0) && (f == 2));
            int contrib;
            if (ball) {
                int l = __ffs(ball) - 1;
                contrib = (lane <= l) ? val : 0;
            } else {
                contrib = (jj >= 0) ? val : 0;
            }
#pragma unroll
            for (int o = 16; o; o >>= 1) contrib += __shfl_xor_sync(0xffffffffu, contrib, o);
            excl += contrib;
            if (ball) break;
            j -= 32;
        }
        if (lane == 0) {
            sh_exc = excl;
            g_bpre[bid] = excl + sh_total;
            __threadfence();
            g_bflag[bid] = 2;
        }
    }
    __syncthreads();

    int exc = sh_exc;
#pragma unroll
    for (int r = 0; r < 4; r++) {
        int i = base + r;
        if (i < NN) {
            int rp = run + exc;
            g_rowptr[i] = rp;
            g_cursor[i] = rp;
            g_dinv[i] = rsqrtf((float)g_deg[i] + 1.0f);
        }
        run += v[r];
    }
    if (bid == 0 && t == 0) g_rowptr[NN] = EE;
}

__global__ void k_fill(const void* __restrict__ ei) {
    int e2 = blockIdx.x * blockDim.x + threadIdx.x;
    if (e2 < EE / 2) {
        int2 s = edge_pair(ei, (size_t)e2);
        int2 d = edge_pair(ei, (size_t)(EE / 2) + e2);
        int p0 = atomicAdd(&g_cursor[d.x], 1);
        g_col[p0] = s.x;
        int p1 = atomicAdd(&g_cursor[d.y], 1);
        g_col[p1] = s.y;
    }
}

// pack float4 -> 4 halves (uint2)
__device__ __forceinline__ uint2 pack_h4(float a, float b, float c, float d) {
    __half2 lo = __floats2half2_rn(a, b);
    __half2 hi = __floats2half2_rn(c, d);
    uint2 r;
    r.x = *(unsigned*)&lo;
    r.y = *(unsigned*)&hi;
    return r;
}

// ---------------- fused encoders + GCN0 linear : hs0 = fp16(dinv .* (relu-concat @ W0)) ----------------
// 512 threads, 64-node tile, xs stored fp16 -> 91.4KB smem -> 2 CTAs/SM (32 warps).
#define XS_STRIDE 200   // halves per row (192 + 8 pad)
__global__ void __launch_bounds__(512) k_enc0(
    const float* __restrict__ xf, const float* __restrict__ xw, const float* __restrict__ xt,
    const float* __restrict__ wf, const float* __restrict__ bfir,
    const float* __restrict__ ww, const float* __restrict__ bwea,
    const float* __restrict__ wt, const float* __restrict__ bter,
    const float* __restrict__ W0)
{
    extern __shared__ __align__(16) float sm[];
    float* Ws   = sm;            // 192*64 = 12288 f
    float* Wenc = Ws + 12288;    // 1920 f
    float* Benc = Wenc + 1920;   // 192 f
    float* raw  = Benc + 192;    // 64*32 = 2048 f
    __half* xsh = (__half*)(raw + 2048);   // 64*200 halves = 25600 B
    const int t = threadIdx.x;

    for (int i = t; i < 12288; i += 512) Ws[i] = W0[i];
    for (int i = t; i < 512;  i += 512) Wenc[i] = wf[i];
    for (int i = t; i < 768;  i += 512) Wenc[512 + i] = ww[i];
    for (int i = t; i < 640;  i += 512) Wenc[1280 + i] = wt[i];
    if (t < 64) { Benc[t] = bfir[t]; Benc[64 + t] = bwea[t]; Benc[128 + t] = bter[t]; }

    const int n0g = blockIdx.x * 64;
    for (int i = t; i < 512; i += 512) { int n = i >> 3, k = i & 7;  int gn = n0g + n; raw[n * 32 + k]      = (gn < NN) ? xf[gn * 8 + k]  : 0.f; }
    for (int i = t; i < 768; i += 512) { int n = i / 12, k = i % 12; int gn = n0g + n; raw[n * 32 + 8 + k]  = (gn < NN) ? xw[gn * 12 + k] : 0.f; }
    for (int i = t; i < 640; i += 512) { int n = i / 10, k = i % 10; int gn = n0g + n; raw[n * 32 + 20 + k] = (gn < NN) ? xt[gn * 10 + k] : 0.f; }
    __syncthreads();

    // stage A: per-node 192-dim encoded features, written as fp16
    for (int i = t; i < 12288; i += 512) {
        int n = i / 192, c = i % 192;
        int mod = c >> 6, cc = c & 63;
        int koff = (mod == 0) ? 0 : ((mod == 1) ? 8 : 20);
        int kn   = (mod == 0) ? 8 : ((mod == 1) ? 12 : 10);
        const float* wr = Wenc + ((mod == 0) ? 0 : ((mod == 1) ? 512 : 1280));
        float v = Benc[c];
        for (int k = 0; k < kn; k++) v = fmaf(raw[n * 32 + koff + k], wr[k * 64 + cc], v);
        xsh[n * XS_STRIDE + c] = __float2half(fmaxf(v, 0.f));
    }
    __syncthreads();

    // stage B: 64x64 tile, 2x4 micro-tile, half2 A-loads (2 k per load), packed f32x2 FMA
    const int cg = t & 15, rg = t >> 4;     // rg: 0..31
    const int n0 = rg * 2, c0 = cg * 4;
    unsigned long long acc01[2] = {0, 0}, acc23[2] = {0, 0};
    const __half2* x0 = (const __half2*)&xsh[n0 * XS_STRIDE];
    const __half2* x1 = (const __half2*)&xsh[(n0 + 1) * XS_STRIDE];

#pragma unroll 2
    for (int k2 = 0; k2 < 96; k2++) {
        const int k = k2 * 2;
        float4 bA = *(const float4*)&Ws[k * 64 + c0];
        float4 bB = *(const float4*)&Ws[(k + 1) * 64 + c0];
        unsigned long long bA01, bA23, bB01, bB23;
        PK2(bA01, bA.x, bA.y);
        PK2(bA23, bA.z, bA.w);
        PK2(bB01, bB.x, bB.y);
        PK2(bB23, bB.z, bB.w);
        float2 a0 = __half22float2(x0[k2]);
        float2 a1 = __half22float2(x1[k2]);
        unsigned long long t0, t1;
        PK2(t0, a0.x, a0.x);
        FMA2(acc01[0], t0, bA01);
        FMA2(acc23[0], t0, bA23);
        PK2(t1, a0.y, a0.y);
        FMA2(acc01[0], t1, bB01);
        FMA2(acc23[0], t1, bB23);
        PK2(t0, a1.x, a1.x);
        FMA2(acc01[1], t0, bA01);
        FMA2(acc23[1], t0, bA23);
        PK2(t1, a1.y, a1.y);
        FMA2(acc01[1], t1, bB01);
        FMA2(acc23[1], t1, bB23);
    }
#pragma unroll
    for (int i = 0; i < 2; i++) {
        int gn = n0g + n0 + i;
        if (gn < NN) {
            float di = g_dinv[gn];
            float a0, a1, a2, a3;
            UPK2(a0, a1, acc01[i]);
            UPK2(a2, a3, acc23[i]);
            uint2 o = pack_h4(di * a0, di * a1, di * a2, di * a3);
            *(uint2*)&g_hs[(size_t)gn * 64 + c0] = o;
        }
    }
}

// ---------------- GCN linear : hs = fp16(dinv .* (x @ W)) , packed f32x2 FMA ----------------
__global__ void __launch_bounds__(256) k_lin(const float* __restrict__ W)
{
    __shared__ __align__(16) float Ws[4096];
    __shared__ __align__(16) float xs[128 * 68];
    const int t = threadIdx.x;
    for (int i = t; i < 4096; i += 256) Ws[i] = W[i];

    const int n0g = blockIdx.x * 128;
    for (int i = t; i < 2048; i += 256) {
        int n = i >> 4, k4 = i & 15;
        int gn = n0g + n;
        float4 v = (gn < NN) ? *(const float4*)&g_x[(size_t)gn * 64 + k4 * 4] : make_float4(0, 0, 0, 0);
        *(float4*)&xs[n * 68 + k4 * 4] = v;
    }
    __syncthreads();

    const int cg = t & 15, rg = t >> 4;
    const int n0 = rg * 8, c0 = cg * 4;
    unsigned long long acc01[8], acc23[8];
#pragma unroll
    for (int i = 0; i < 8; i++) { acc01[i] = 0; acc23[i] = 0; }

#pragma unroll 4
    for (int k = 0; k < 64; k++) {
        float4 b = *(const float4*)&Ws[k * 64 + c0];
        unsigned long long b01, b23;
        PK2(b01, b.x, b.y);
        PK2(b23, b.z, b.w);
#pragma unroll
        for (int i = 0; i < 8; i++) {
            float a = xs[(n0 + i) * 68 + k];
            unsigned long long aa;
            PK2(aa, a, a);
            FMA2(acc01[i], aa, b01);
            FMA2(acc23[i], aa, b23);
        }
    }
#pragma unroll
    for (int i = 0; i < 8; i++) {
        int gn = n0g + n0 + i;
        if (gn < NN) {
            float di = g_dinv[gn];
            float a0, a1, a2, a3;
            UPK2(a0, a1, acc01[i]);
            UPK2(a2, a3, acc23[i]);
            uint2 o = pack_h4(di * a0, di * a1, di * a2, di * a3);
            *(uint2*)&g_hs[(size_t)gn * 64 + c0] = o;
        }
    }
}

// ---------------- gather aggregation : x = relu(dinv_i * (sum_j hs_j + hs_i) + b) ----------------
__global__ void __launch_bounds__(256) k_gather(const float* __restrict__ bias)
{
    const int lane = threadIdx.x & 31;
    const int warp = threadIdx.x >> 5;
    const int q  = lane >> 3;
    const int ql = lane & 7;
    const int node = blockIdx.x * 32 + warp * 4 + q;

    const int beg = g_rowptr[node], end = g_rowptr[node + 1];

    uint4 self = *(const uint4*)&g_hs[(size_t)node * 64 + ql * 8];
    float2 a0 = __half22float2(*(__half2*)&self.x);
    float2 a1 = __half22float2(*(__half2*)&self.y);
    float2 a2 = __half22float2(*(__half2*)&self.z);
    float2 a3 = __half22float2(*(__half2*)&self.w);

    int p = beg;
    while (true) {
        int rem = end - p;
        int mx = rem;
        mx = max(mx, __shfl_xor_sync(0xffffffffu, mx, 8));
        mx = max(mx, __shfl_xor_sync(0xffffffffu, mx, 16));
        if (mx <= 0) break;
        int cnt = min(8, max(rem, 0));
        int idx = (ql < cnt) ? g_col[p + ql] : 0;

        uint4 v[8];
#pragma unroll
        for (int r = 0; r < 8; r++) {
            int j = __shfl_sync(0xffffffffu, idx, (q << 3) + r);
            v[r] = (r < cnt) ? *(const uint4*)&g_hs[(size_t)j * 64 + ql * 8]
                             : make_uint4(0u, 0u, 0u, 0u);
        }
#pragma unroll
        for (int r = 0; r < 8; r++) {
            float2 v0 = __half22float2(*(__half2*)&v[r].x);
            float2 v1 = __half22float2(*(__half2*)&v[r].y);
            float2 v2 = __half22float2(*(__half2*)&v[r].z);
            float2 v3 = __half22float2(*(__half2*)&v[r].w);
            a0.x += v0.x; a0.y += v0.y;
            a1.x += v1.x; a1.y += v1.y;
            a2.x += v2.x; a2.y += v2.y;
            a3.x += v3.x; a3.y += v3.y;
        }
        p += 8;
    }

    float di = g_dinv[node];
    float4 bA = *(const float4*)&bias[ql * 8];
    float4 bB = *(const float4*)&bias[ql * 8 + 4];
    float4 oA, oB;
    oA.x = fmaxf(fmaf(di, a0.x, bA.x), 0.f);
    oA.y = fmaxf(fmaf(di, a0.y, bA.y), 0.f);
    oA.z = fmaxf(fmaf(di, a1.x, bA.z), 0.f);
    oA.w = fmaxf(fmaf(di, a1.y, bA.w), 0.f);
    oB.x = fmaxf(fmaf(di, a2.x, bB.x), 0.f);
    oB.y = fmaxf(fmaf(di, a2.y, bB.y), 0.f);
    oB.z = fmaxf(fmaf(di, a3.x, bB.z), 0.f);
    oB.w = fmaxf(fmaf(di, a3.y, bB.w), 0.f);
    *(float4*)&g_x[(size_t)node * 64 + ql * 8]     = oA;
    *(float4*)&g_x[(size_t)node * 64 + ql * 8 + 4] = oB;
}

// ---------------- output MLP : out = relu(x @ W1 + b1) @ W2 + b2 (128 nodes/block) ----------------
__global__ void __launch_bounds__(256) k_out(
    const float* __restrict__ W1, const float* __restrict__ B1,
    const float* __restrict__ W2, const float* __restrict__ B2,
    float* __restrict__ out)
{
    __shared__ float W1s[2048];
    __shared__ float W2s[32];
    __shared__ float B1s[32];
    __shared__ float xsh[8][64];
    const int t = threadIdx.x;
    for (int i = t; i < 2048; i += 256) W1s[i] = W1[i];
    if (t < 32) { W2s[t] = W2[t]; B1s[t] = B1[t]; }
    __syncthreads();

    const int lane = t & 31, w = t >> 5;
#pragma unroll 1
    for (int it = 0; it < 16; it++) {
        const int node = blockIdx.x * 128 + it * 8 + w;
        if (node < NN) {
            xsh[w][lane]      = g_x[(size_t)node * 64 + lane];
            xsh[w][32 + lane] = g_x[(size_t)node * 64 + 32 + lane];
            __syncwarp();
            float m = B1s[lane];
#pragma unroll
            for (int k = 0; k < 64; k++) m = fmaf(xsh[w][k], W1s[k * 32 + lane], m);
            m = fmaxf(m, 0.f) * W2s[lane];
#pragma unroll
            for (int off = 16; off; off >>= 1) m += __shfl_xor_sync(0xffffffffu, m, off);
            if (lane == 0) out[node] = m + B2[0];
            __syncwarp();
        }
    }
}

// ---------------- launch ----------------
extern "C" void kernel_launch(void* const* d_in, const int* in_sizes, int n_in,
                              void* d_out, int out_size)
{
    const float* xf  = (const float*)d_in[0];
    const float* xw  = (const float*)d_in[1];
    const float* xt  = (const float*)d_in[2];
    const void*  ei  = d_in[3];
    const float* wf  = (const float*)d_in[4];
    const float* bf  = (const float*)d_in[5];
    const float* ww  = (const float*)d_in[6];
    const float* bw  = (const float*)d_in[7];
    const float* wt  = (const float*)d_in[8];
    const float* bt  = (const float*)d_in[9];
    const float* w0  = (const float*)d_in[10];
    const float* b0  = (const float*)d_in[11];
    const float* w1  = (const float*)d_in[12];
    const float* b1  = (const float*)d_in[13];
    const float* w2  = (const float*)d_in[14];
    const float* b2  = (const float*)d_in[15];
    const float* ow1 = (const float*)d_in[16];
    const float* ob1 = (const float*)d_in[17];
    const float* ow2 = (const float*)d_in[18];
    const float* ob2 = (const float*)d_in[19];
    float* out = (float*)d_out;

    // Ws 12288f + Wenc 1920f + Benc 192f + raw 2048f = 65792 B ; xs fp16 = 25600 B
    const int ENC_SMEM = (12288 + 1920 + 192 + 2048) * 4 + 64 * XS_STRIDE * 2;  // 91392 B
    cudaFuncSetAttribute(k_enc0, cudaFuncAttributeMaxDynamicSharedMemorySize, ENC_SMEM);

    const int encTiles = (NN + 63) / 64;     // 1563
    const int linTiles = (NN + 127) / 128;   // 782
    const int gBlocks  = NN / 32;            // 3125
    const int oBlocks  = (NN + 127) / 128;   // 782
    const int ePairs   = EE / 2;

    // CSR build; enc0 kept at ncu capture slot 3 to verify the 2-CTA occupancy fix
    k_prep<<<(NN + 255) / 256, 256>>>((const int*)ei);
    k_deg<<<(ePairs + 255) / 256, 256>>>(ei);
    k_scan<<<NBSCAN, 256>>>();
    k_enc0<<<encTiles, 512, ENC_SMEM>>>(xf, xw, xt, wf, bf, ww, bw, wt, bt, w0);  // slot 3
    k_fill<<<(ePairs + 255) / 256, 256>>>(ei);

    // layer 0 gather
    k_gather<<<gBlocks, 256>>>(b0);
    // layer 1
    k_lin<<<linTiles, 256>>>(w1);
    k_gather<<<gBlocks, 256>>>(b1);
    // layer 2
    k_lin<<<linTiles, 256>>>(w2);
    k_gather<<<gBlocks, 256>>>(b2);
    // output MLP
    k_out<<<oBlocks, 256>>>(ow1, ob1, ow2, ob2, out);
}